// round 12
// baseline (speedup 1.0000x reference)
#include <cuda_runtime.h>
#include <cuda_fp16.h>
#include <math.h>
#include <stdint.h>

#define BATCH 16
#define CCH   256
#define HW    4096
#define HEADS 8
#define DH    64
#define HID   512
#define OQKV  1536
#define BHN   (BATCH*HEADS)   /* 128 */
#define QSCALE 0.125f
#define LNEPS  1e-5f
#define INV_N  (1.0f/4096.0f)
#define SPAD  40   /* smem row pitch in fp16: 80B -> 8 ldmatrix rows hit distinct banks */
#define A3SCALE    262144.0f          /* 2^18: lifts a3 (~4e-6) into fp16 normal range */
#define A3UNSCALE  (1.0f/262144.0f)

// ==================== scratch (device globals; no allocations) ====================
__device__ __align__(256) float g_stat1[BATCH*HW*2];            // (mu, rstd) input LN
__device__ __align__(256) float g_ws[OQKV];                     // row sums of fp16 w_eff
__device__ __align__(256) __half g_w1[OQKV*CCH];                // (w_qkv*g) fp16 [o][c] K-major
__device__ __align__(256) __half g_w2[CCH*HID];                 // w_out fp16 [o][he] K-major
__device__ __align__(256) __half g_fT[(size_t)BATCH*HW*CCH];    // feature^T fp16 [b][p][c]
__device__ __align__(256) __half g_kv[(size_t)BATCH*1024*HW];   // k'=exp(k-Mtile) ch 0-511, v'=v*invn 512-1023
__device__ __align__(256) __half g_qs[(size_t)BHN*HW*DH];       // softmaxed q fp16 [bh][p2][d]
__device__ __align__(256) float g_kpm[32*BHN*DH];               // per-tile partial max
__device__ __align__(256) float g_kps[32*BHN*DH];               // per-tile partial sumexp
__device__ __align__(256) float g_kmax[BHN*DH];
__device__ __align__(256) float g_ksum[BHN*DH];
__device__ __align__(256) float g_ctxp[8*BHN*DH*DH];
__device__ __align__(256) float g_ctx[BHN*DH*DH];
__device__ __align__(256) __half g_a3[(size_t)BATCH*HW*HID];    // [b][p][he] fp16 (x 2^18)

// ==================== helpers (sm_80+ PTX, valid on sm_100) ====================
__device__ __forceinline__ uint32_t smem_u32(const void* p) {
    uint32_t a;
    asm("{ .reg .u64 t; cvta.to.shared.u64 t, %1; cvt.u32.u64 %0, t; }" : "=r"(a) : "l"(p));
    return a;
}
__device__ __forceinline__ void ldmx4(uint32_t* r, uint32_t a) {
    asm volatile("ldmatrix.sync.aligned.m8n8.x4.shared.b16 {%0,%1,%2,%3}, [%4];"
        : "=r"(r[0]), "=r"(r[1]), "=r"(r[2]), "=r"(r[3]) : "r"(a));
}
__device__ __forceinline__ void mma_f16(float* d, const uint32_t* a, uint32_t b0, uint32_t b1) {
    asm volatile("mma.sync.aligned.m16n8k16.row.col.f32.f16.f16.f32 "
        "{%0,%1,%2,%3}, {%4,%5,%6,%7}, {%8,%9}, {%0,%1,%2,%3};"
        : "+f"(d[0]), "+f"(d[1]), "+f"(d[2]), "+f"(d[3])
        : "r"(a[0]), "r"(a[1]), "r"(a[2]), "r"(a[3]), "r"(b0), "r"(b1));
}
__device__ __forceinline__ void cp16(uint32_t s, const void* g) {
    asm volatile("cp.async.cg.shared.global [%0], [%1], 16;" :: "r"(s), "l"(g) : "memory");
}
#define CP_COMMIT() asm volatile("cp.async.commit_group;" ::: "memory")
#define CP_WAIT1()  asm volatile("cp.async.wait_group 1;" ::: "memory")
#define CP_WAIT0()  asm volatile("cp.async.wait_group 0;" ::: "memory")

// ==================== weight prep (single fp16) ====================
__global__ void __launch_bounds__(256) prep_w1b(const float* __restrict__ wqkv,
                                                const float* __restrict__ gin) {
    int o = blockIdx.x, c = threadIdx.x;
    float w = wqkv[o*CCH + c] * gin[c];
    __half h = __float2half_rn(w);
    g_w1[o*CCH + c] = h;
    float we = __half2float(h);
    __shared__ float red[256];
    red[c] = we; __syncthreads();
    for (int s = 128; s > 0; s >>= 1) { if (c < s) red[c] += red[c+s]; __syncthreads(); }
    if (c == 0) g_ws[o] = red[0];
}

__global__ void __launch_bounds__(256) prep_w2b(const float* __restrict__ wout) {
    int o = blockIdx.x;
    for (int t = threadIdx.x; t < HID; t += 256)
        g_w2[o*HID + t] = __float2half_rn(wout[o*HID + t]);
}

// ==================== feature transpose + fp16 + LN stats (fused) ====================
__global__ void __launch_bounds__(256) conv_feat(const float* __restrict__ feat) {
    __shared__ float S[128][65];
    __shared__ float s_s[256], s_ss[256];
    int p0 = blockIdx.x*64, b = blockIdx.y;
    int tid = threadIdx.x;
    float sum = 0.f, ssum = 0.f;
    for (int h = 0; h < 2; h++) {
        #pragma unroll
        for (int i = 0; i < 32; i++) {
            int idx = tid + (i<<8);
            int cl = idx >> 6, pl = idx & 63;
            float v = feat[((size_t)(b*CCH + h*128 + cl))*HW + p0 + pl];
            S[cl][pl] = v;
            sum += v; ssum = fmaf(v, v, ssum);
        }
        __syncthreads();
        #pragma unroll
        for (int i = 0; i < 32; i++) {
            int idx = tid + (i<<8);
            int pl = idx >> 7, cl = idx & 127;
            g_fT[((size_t)b*HW + p0 + pl)*CCH + h*128 + cl] = __float2half_rn(S[cl][pl]);
        }
        __syncthreads();
    }
    s_s[tid] = sum; s_ss[tid] = ssum;
    __syncthreads();
    if (tid < 64) {
        float s  = s_s[tid] + s_s[tid+64] + s_s[tid+128] + s_s[tid+192];
        float ss = s_ss[tid] + s_ss[tid+64] + s_ss[tid+128] + s_ss[tid+192];
        float mu = s * (1.f/CCH);
        float var = fmaf(-mu, mu, ss * (1.f/CCH));
        ((float2*)g_stat1)[(size_t)b*HW + p0 + tid] = make_float2(mu, rsqrtf(var + LNEPS));
    }
}

// ==================== warp-MMA GEMM: 4 warps, 64x64 warp tiles, 3-stage cp.async ====================
// G1=true : TM=128,TN=128,K=256. Epilogue by qkv region (q-softmax / k-exp+partials / v-norm).
// G1=false: TM=256,TN=64, K=512. Epilogue = unscale 2^-18 + full output LN -> d_out.
template<int TM, int TN, int KTOT, bool G1>
__global__ void __launch_bounds__(128, 2) gemm_p(float* __restrict__ Cext,
                                                 const float* __restrict__ gout) {
    extern __shared__ char smem[];
    constexpr int WN     = TN/64;               // warps along n (G1:2, G4:1)
    constexpr int A_ARR  = TM*SPAD*2;
    constexpr int B_ARR  = TN*SPAD*2;
    constexpr int STAGE  = A_ARR + B_ARR;
    constexpr int BUFB   = TM*(G1 ? (TN+2) : (TN+4))*4;
    constexpr int FIX    = (3*STAGE > BUFB) ? 3*STAGE : BUFB;
    constexpr int KC     = KTOT/32;

    int tid = threadIdx.x, wid = tid >> 5, lane = tid & 31;
    int b = blockIdx.z, m0 = blockIdx.y*TM, n0 = blockIdx.x*TN;
    int wm = wid / WN, wn = wid % WN;
    uint32_t sb = smem_u32(smem);

    const __half* Ap = (G1 ? g_w1 : g_w2) + (size_t)m0*KTOT;
    const __half* Bp = (G1 ? g_fT : g_a3) + ((size_t)b*HW + n0)*KTOT;

    float2* sstat = (float2*)(smem + FIX);          // G1
    float*  sws   = (float*)(smem + FIX + 1024);    // G1
    float*  sg    = (float*)(smem + FIX);           // G4
    float*  ps    = (float*)(smem + FIX + 1024);    // G4
    float*  pss   = (float*)(smem + FIX + 2048);    // G4
    float2* mrs   = (float2*)(smem + FIX + 3072);   // G4

    if (G1) {
        sstat[tid] = ((const float2*)g_stat1)[(size_t)b*HW + n0 + tid];
        sws[tid]   = g_ws[m0 + tid];
    } else {
        sg[tid] = gout[tid];
        sg[tid + 128] = gout[tid + 128];
    }

    auto load_stage = [&](int kc, int s) {
        #pragma unroll
        for (int i = 0; i < TM/32; i++) {             // A
            int e = tid + (i << 7);
            int r = e >> 2, q = e & 3;
            cp16(sb + s*STAGE + (r*SPAD + q*8)*2, Ap + (size_t)r*KTOT + kc*32 + q*8);
        }
        #pragma unroll
        for (int i = 0; i < TN/32; i++) {             // B
            int e = tid + (i << 7);
            int r = e >> 2, q = e & 3;
            cp16(sb + s*STAGE + A_ARR + (r*SPAD + q*8)*2, Bp + (size_t)r*KTOT + kc*32 + q*8);
        }
    };

    float acc[4][8][4] = {};
    int lrow = (lane & 7) + (((lane >> 3) & 1) << 3);
    int lcol = (lane >> 4) << 3;

    auto compute_stage = [&](int s) {
        uint32_t sbase = sb + s*STAGE;
        #pragma unroll
        for (int ks = 0; ks < 2; ks++) {
            int kof = ks*16 + lcol;
            uint32_t bf[4][4];
            #pragma unroll
            for (int bt = 0; bt < 4; bt++) {
                int row = wn*64 + bt*16 + lrow;
                ldmx4(bf[bt], sbase + A_ARR + (row*SPAD + kof)*2);
            }
            #pragma unroll
            for (int mt = 0; mt < 4; mt++) {
                uint32_t af[4];
                int row = wm*64 + mt*16 + lrow;
                ldmx4(af, sbase + (row*SPAD + kof)*2);
                #pragma unroll
                for (int nt = 0; nt < 8; nt++) {
                    int bt = nt >> 1, od = nt & 1;
                    mma_f16(acc[mt][nt], af, bf[bt][od], bf[bt][od+2]);
                }
            }
        }
    };

    // 3-stage pipeline, one barrier per chunk
    load_stage(0, 0); CP_COMMIT();
    load_stage(1, 1); CP_COMMIT();
    int sl = 2, sc = 0;
    for (int kc = 0; kc < KC; kc++) {
        if (kc + 1 < KC) { CP_WAIT1(); } else { CP_WAIT0(); }
        __syncthreads();
        if (kc + 2 < KC) {
            load_stage(kc+2, sl); CP_COMMIT();
            if (++sl == 3) sl = 0;
        }
        compute_stage(sc);
        if (++sc == 3) sc = 0;
    }
    __syncthreads();

    if (G1) {
        float* buf = (float*)smem;   // 128 x 128, pitch 130
        #pragma unroll
        for (int mt = 0; mt < 4; mt++) {
            int rml = wm*64 + mt*16 + (lane >> 2);
            float w0 = sws[rml], w1 = sws[rml+8];
            #pragma unroll
            for (int nt = 0; nt < 8; nt++) {
                int cl = wn*64 + nt*8 + 2*(lane & 3);
                float* d = acc[mt][nt];
                float2 s0 = sstat[cl], s1 = sstat[cl+1];
                buf[rml*130 + cl]       = s0.y*(d[0] - s0.x*w0);
                buf[rml*130 + cl + 1]   = s1.y*(d[1] - s1.x*w0);
                buf[(rml+8)*130 + cl]     = s0.y*(d[2] - s0.x*w1);
                buf[(rml+8)*130 + cl + 1] = s1.y*(d[3] - s1.x*w1);
            }
        }
        __syncthreads();
        int region = blockIdx.y >> 2;
        if (region == 0) {
            // q: softmax over d + spatial-transpose store to g_qs (fp16)
            int col = tid;
            int p = n0 + col, h2 = p >> 6, wi = p & 63;
            #pragma unroll
            for (int g = 0; g < 2; g++) {
                int bh = b*8 + blockIdx.y*2 + g;
                float mx = -1e30f;
                #pragma unroll 8
                for (int d = 0; d < 64; d++) mx = fmaxf(mx, buf[(g*64+d)*130 + col]);
                float sum = 0.f;
                #pragma unroll 8
                for (int d = 0; d < 64; d++) {
                    float e = __expf(buf[(g*64+d)*130 + col] - mx);
                    buf[(g*64+d)*130 + col] = e;
                    sum += e;
                }
                float r = QSCALE / sum;
                uint4* dst = (uint4*)&g_qs[((size_t)bh*HW + wi*64 + h2)*DH];
                #pragma unroll
                for (int d8 = 0; d8 < 8; d8++) {
                    __half2 h0 = __floats2half2_rn(buf[(g*64+d8*8+0)*130+col]*r, buf[(g*64+d8*8+1)*130+col]*r);
                    __half2 h1 = __floats2half2_rn(buf[(g*64+d8*8+2)*130+col]*r, buf[(g*64+d8*8+3)*130+col]*r);
                    __half2 h2v= __floats2half2_rn(buf[(g*64+d8*8+4)*130+col]*r, buf[(g*64+d8*8+5)*130+col]*r);
                    __half2 h3 = __floats2half2_rn(buf[(g*64+d8*8+6)*130+col]*r, buf[(g*64+d8*8+7)*130+col]*r);
                    uint4 u;
                    u.x = *(uint32_t*)&h0; u.y = *(uint32_t*)&h1;
                    u.z = *(uint32_t*)&h2v; u.w = *(uint32_t*)&h3;
                    dst[d8] = u;
                }
            }
        } else if (region == 1) {
            // k: per-row tile max, then store exp(k - Mtile) fp16 + online partials
            int row = tid;
            float M = -1e30f;
            #pragma unroll 8
            for (int c = 0; c < 128; c++) M = fmaxf(M, buf[row*130 + c]);
            __half2* kvb = (__half2*)(g_kv + ((size_t)(b*1024 + (m0 - 512)))*HW + n0);
            float s = 0.f;
            #pragma unroll 8
            for (int c2 = 0; c2 < 64; c2++) {
                float e0 = __expf(buf[row*130 + 2*c2]     - M);
                float e1 = __expf(buf[row*130 + 2*c2 + 1] - M);
                s += e0 + e1;
                kvb[(size_t)row*(HW/2) + c2] = __floats2half2_rn(e0, e1);
            }
            int ch = (blockIdx.y - 4)*128 + row;
            int r = (b*8 + (ch >> 6))*64 + (ch & 63);
            g_kpm[blockIdx.x*(BHN*DH) + r] = M;
            g_kps[blockIdx.x*(BHN*DH) + r] = s;
        } else {
            // v: per-pixel inverse norm, then store v*invn fp16
            float* sinv2 = (float*)(smem + FIX);  // reuse sstat area (256 floats)
            int col = tid;
            #pragma unroll
            for (int g = 0; g < 2; g++) {
                float ss = 0.f;
                #pragma unroll 8
                for (int d = 0; d < 64; d++) {
                    float v = buf[(g*64+d)*130 + col];
                    ss = fmaf(v, v, ss);
                }
                sinv2[g*128 + col] = 1.f / fmaxf(sqrtf(ss), 1e-12f);
            }
            __syncthreads();
            __half2* kvb = (__half2*)(g_kv + ((size_t)(b*1024 + (m0 - 512)))*HW + n0);
            #pragma unroll 8
            for (int i = 0; i < 64; i++) {
                int idx = tid + (i << 7);
                int row = idx >> 6, c2 = idx & 63;
                int gg = row >> 6;
                float v0 = buf[row*130 + 2*c2]     * sinv2[gg*128 + 2*c2];
                float v1 = buf[row*130 + 2*c2 + 1] * sinv2[gg*128 + 2*c2 + 1];
                kvb[(size_t)row*(HW/2) + c2] = __floats2half2_rn(v0, v1);
            }
        }
    } else {
        // G4 epilogue: unscale a3 factor, then full output LN over 256 channels
        float* buf = (float*)smem;   // 256 x 64, pitch 68
        float* Cb = Cext + ((size_t)(b*CCH + m0))*HW + n0;
        #pragma unroll
        for (int mt = 0; mt < 4; mt++) {
            int rml = wm*64 + mt*16 + (lane >> 2);
            #pragma unroll
            for (int nt = 0; nt < 8; nt++) {
                int cl = nt*8 + 2*(lane & 3);
                float* d = acc[mt][nt];
                buf[rml*68 + cl]     = d[0] * A3UNSCALE;
                buf[rml*68 + cl + 1] = d[1] * A3UNSCALE;
                buf[(rml+8)*68 + cl]     = d[2] * A3UNSCALE;
                buf[(rml+8)*68 + cl + 1] = d[3] * A3UNSCALE;
            }
        }
        __syncthreads();
        {
            int col = tid & 63, part = tid >> 6;   // part in {0,1}, 128 rows each
            float s = 0.f, ss = 0.f;
            #pragma unroll 8
            for (int r = part*128; r < part*128 + 128; r++) {
                float v = buf[r*68 + col];
                s += v; ss = fmaf(v, v, ss);
            }
            ps[part*64 + col] = s;
            pss[part*64 + col] = ss;
        }
        __syncthreads();
        if (tid < 64) {
            float s  = ps[tid] + ps[64+tid];
            float ss = pss[tid] + pss[64+tid];
            float mu = s * (1.f/CCH);
            float var = fmaf(-mu, mu, ss * (1.f/CCH));
            mrs[tid] = make_float2(mu, rsqrtf(var + LNEPS));
        }
        __syncthreads();
        #pragma unroll 8
        for (int i = 0; i < 128; i++) {
            int idx = tid + (i << 7);
            int row = idx >> 6, col = idx & 63;
            float2 st = mrs[col];
            Cb[(size_t)row*HW + col] = (buf[row*68 + col] - st.x) * st.y * sg[row];
        }
    }
}

// ==================== merge k-softmax partials over 32 tiles ====================
__global__ void __launch_bounds__(256) kmerge() {
    int r = blockIdx.x*8 + (threadIdx.x >> 5);
    int lane = threadIdx.x & 31;
    float m = g_kpm[lane*(BHN*DH) + r];
    float s = g_kps[lane*(BHN*DH) + r];
    float M = m;
    #pragma unroll
    for (int o = 16; o > 0; o >>= 1) M = fmaxf(M, __shfl_xor_sync(0xffffffffu, M, o));
    float sc = s * __expf(m - M);
    #pragma unroll
    for (int o = 16; o > 0; o >>= 1) sc += __shfl_xor_sync(0xffffffffu, sc, o);
    if (lane == 0) { g_kmax[r] = M; g_ksum[r] = sc; }
}

// ==================== context partials: tensor-core MMA over exp'd k / scaled v ====================
#define G2PITCH 136
#define G2TILE  (64*G2PITCH*2)    /* 17408 B per operand tile */
#define G2STG   (2*G2TILE)        /* 34816 B per stage */
#define SMEM_G2 (2*G2STG)         /* 69632 B */

__global__ void __launch_bounds__(256, 2) gemm2() {
    extern __shared__ char smem[];
    uint32_t sb = smem_u32(smem);
    int sp = blockIdx.x, bh = blockIdx.y;
    int b = bh >> 3, head = bh & 7;
    int tid = threadIdx.x, wid = tid >> 5, lane = tid & 31;
    int wm = wid >> 1, wn = wid & 1;
    const __half* kbase = g_kv + ((size_t)(b*1024 + head*DH))*HW;
    const __half* vbase = g_kv + ((size_t)(b*1024 + 512 + head*DH))*HW;
    int n0 = sp*512;

    int r0 = wm*16 + (lane >> 2), r1 = r0 + 8;
    float km0 = g_kmax[bh*64 + r0], km1 = g_kmax[bh*64 + r1];
    float rs0 = 1.f / g_ksum[bh*64 + r0], rs1 = 1.f / g_ksum[bh*64 + r1];

    auto load_blk = [&](int blk, int s) {
        int nb = n0 + blk*128;
        #pragma unroll
        for (int i = 0; i < 8; i++) {
            int e = tid + (i << 8);
            int isv = e >= 1024;
            int rq = e & 1023;
            int r = rq >> 4, q = rq & 15;
            const __half* src = (isv ? vbase : kbase) + (size_t)r*HW + nb + q*8;
            cp16(sb + s*G2STG + isv*G2TILE + (r*G2PITCH + q*8)*2, src);
        }
    };

    float accT[4][4] = {};
    int lrow = (lane & 7) + (((lane >> 3) & 1) << 3);
    int lcol = (lane >> 4) << 3;

    load_blk(0, 0); CP_COMMIT();
    for (int blk = 0; blk < 4; blk++) {
        if (blk + 1 < 4) { load_blk(blk+1, (blk+1) & 1); }
        CP_COMMIT();
        if (blk + 1 < 4) { CP_WAIT1(); } else { CP_WAIT0(); }
        __syncthreads();
        uint32_t base = sb + (blk & 1)*G2STG;
        float accB[4][4] = {};
        #pragma unroll
        for (int ks = 0; ks < 8; ks++) {
            int kof = ks*16 + lcol;
            uint32_t af[4];
            {
                int row = wm*16 + lrow;
                ldmx4(af, base + (row*G2PITCH + kof)*2);
            }
            uint32_t bf[2][4];
            #pragma unroll
            for (int bt = 0; bt < 2; bt++) {
                int row = wn*32 + bt*16 + lrow;
                ldmx4(bf[bt], base + G2TILE + (row*G2PITCH + kof)*2);
            }
            #pragma unroll
            for (int nt = 0; nt < 4; nt++) {
                int bt = nt >> 1, od = nt & 1;
                mma_f16(accB[nt], af, bf[bt][od], bf[bt][od+2]);
            }
        }
        int tile = sp*4 + blk;
        float sc0 = __expf(g_kpm[(size_t)tile*(BHN*DH) + bh*64 + r0] - km0) * rs0;
        float sc1 = __expf(g_kpm[(size_t)tile*(BHN*DH) + bh*64 + r1] - km1) * rs1;
        #pragma unroll
        for (int nt = 0; nt < 4; nt++) {
            accT[nt][0] = fmaf(sc0, accB[nt][0], accT[nt][0]);
            accT[nt][1] = fmaf(sc0, accB[nt][1], accT[nt][1]);
            accT[nt][2] = fmaf(sc1, accB[nt][2], accT[nt][2]);
            accT[nt][3] = fmaf(sc1, accB[nt][3], accT[nt][3]);
        }
        __syncthreads();
    }
    float* cp = g_ctxp + ((size_t)(sp*BHN + bh))*4096;
    #pragma unroll
    for (int nt = 0; nt < 4; nt++) {
        int cl = wn*32 + nt*8 + 2*(lane & 3);
        *(float2*)&cp[r0*64 + cl] = make_float2(accT[nt][0], accT[nt][1]);
        *(float2*)&cp[r1*64 + cl] = make_float2(accT[nt][2], accT[nt][3]);
    }
}

__global__ void __launch_bounds__(256) ctxred() {
    int bh = blockIdx.x, tid = threadIdx.x;
    for (int i = tid; i < 4096; i += 256) {
        float s = 0.f;
        #pragma unroll
        for (int sp = 0; sp < 8; sp++) s += g_ctxp[((size_t)(sp*BHN + bh))*4096 + i];
        g_ctx[(size_t)bh*4096 + i] = s * INV_N;
    }
}

// ==================== out = qs @ ctx -> a3 fp16 (x 2^18) [b][p][he] ====================
__global__ void __launch_bounds__(256) gemm3() {
    __shared__ float Cs[64][64];
    __shared__ float Qs[64][65];
    int p2t = blockIdx.x, bh = blockIdx.y;
    int b = bh >> 3, head = bh & 7;
    int tid = threadIdx.x;
    const float* ctx = g_ctx + (size_t)bh*4096;
    for (int i = tid; i < 4096; i += 256) Cs[i>>6][i&63] = ctx[i];
    const uint2* qb = (const uint2*)(g_qs + ((size_t)bh*HW + p2t*64)*DH);
    #pragma unroll
    for (int i = 0; i < 4; i++) {
        int idx = tid + (i<<8);
        uint2 raw = qb[idx];
        float2 a = __half22float2(*(__half2*)&raw.x);
        float2 c = __half22float2(*(__half2*)&raw.y);
        int lin = idx << 2;
        int row = lin >> 6, col = lin & 63;
        Qs[row][col]   = a.x; Qs[row][col+1] = a.y;
        Qs[row][col+2] = c.x; Qs[row][col+3] = c.y;
    }
    __syncthreads();
    int tx = tid & 15, ty = tid >> 4;
    float acc[4][4] = {};
    #pragma unroll
    for (int d = 0; d < 64; d++) {
        float a0 = Qs[(ty<<2)+0][d], a1 = Qs[(ty<<2)+1][d];
        float a2 = Qs[(ty<<2)+2][d], a3 = Qs[(ty<<2)+3][d];
        float4 bv = *(float4*)&Cs[d][tx<<2];
        acc[0][0]+=a0*bv.x; acc[0][1]+=a0*bv.y; acc[0][2]+=a0*bv.z; acc[0][3]+=a0*bv.w;
        acc[1][0]+=a1*bv.x; acc[1][1]+=a1*bv.y; acc[1][2]+=a1*bv.z; acc[1][3]+=a1*bv.w;
        acc[2][0]+=a2*bv.x; acc[2][1]+=a2*bv.y; acc[2][2]+=a2*bv.z; acc[2][3]+=a2*bv.w;
        acc[3][0]+=a3*bv.x; acc[3][1]+=a3*bv.y; acc[3][2]+=a3*bv.z; acc[3][3]+=a3*bv.w;
    }
    __syncthreads();
    #pragma unroll
    for (int i = 0; i < 4; i++)
        #pragma unroll
        for (int j = 0; j < 4; j++)
            Qs[(ty<<2)+i][(tx<<2)+j] = acc[i][j];   // [p2l][e]
    __syncthreads();
    size_t rowbase = (size_t)b*HW + p2t*64;
    #pragma unroll
    for (int i = 0; i < 16; i++) {
        int idx = tid + (i<<8); int pl = idx >> 6, e = idx & 63;
        g_a3[(rowbase + pl)*HID + head*DH + e] = __float2half_rn(Qs[pl][e] * A3SCALE);
    }
}

// ==================== launch ====================
#define SMEM_G1 68096    /* max(3*20480=61440, 128*130*4=66560) + 1536 */
#define SMEM_G4 80384    /* max(3*25600=76800, 256*68*4=69632)  + 3584 */

extern "C" void kernel_launch(void* const* d_in, const int* in_sizes, int n_in,
                              void* d_out, int out_size) {
    const float* feat = (const float*)d_in[0];
    const float* gin  = (const float*)d_in[1];
    const float* wqkv = (const float*)d_in[2];
    const float* wout = (const float*)d_in[3];
    const float* gout = (const float*)d_in[4];
    float* out = (float*)d_out;

    cudaFuncSetAttribute(gemm_p<128,128,256,true>,
                         cudaFuncAttributeMaxDynamicSharedMemorySize, SMEM_G1);
    cudaFuncSetAttribute(gemm_p<256,64,512,false>,
                         cudaFuncAttributeMaxDynamicSharedMemorySize, SMEM_G4);
    cudaFuncSetAttribute(gemm2,
                         cudaFuncAttributeMaxDynamicSharedMemorySize, SMEM_G2);

    prep_w1b<<<OQKV, 256>>>(wqkv, gin);
    prep_w2b<<<CCH, 256>>>(wout);
    conv_feat<<<dim3(HW/64, BATCH), 256>>>(feat);
    gemm_p<128,128,256,true><<<dim3(HW/128, OQKV/128, BATCH), 128, SMEM_G1>>>(nullptr, nullptr);
    kmerge<<<BHN*DH/8, 256>>>();
    gemm2<<<dim3(8, BHN), 256, SMEM_G2>>>();
    ctxred<<<BHN, 256>>>();
    gemm3<<<dim3(HW/64, BHN), 256>>>();
    gemm_p<256,64,512,false><<<dim3(HW/64, 1, BATCH), 128, SMEM_G4>>>(out, gout);
}

// round 13
// speedup vs baseline: 1.0441x; 1.0441x over previous
#include <cuda_runtime.h>
#include <cuda_fp16.h>
#include <math.h>
#include <stdint.h>

#define BATCH 16
#define CCH   256
#define HW    4096
#define HEADS 8
#define DH    64
#define HID   512
#define OQKV  1536
#define BHN   (BATCH*HEADS)   /* 128 */
#define QSCALE 0.125f
#define LNEPS  1e-5f
#define INV_N  (1.0f/4096.0f)
#define SPAD  40   /* smem row pitch in fp16: 80B -> 8 ldmatrix rows hit distinct banks */
#define A3SCALE    262144.0f          /* 2^18: lifts a3 (~4e-6) into fp16 normal range */
#define A3UNSCALE  (1.0f/262144.0f)

// ==================== scratch (device globals; no allocations) ====================
__device__ __align__(256) float g_stat1[BATCH*HW*2];            // (mu, rstd) input LN
__device__ __align__(256) float g_ws[OQKV];                     // row sums of fp16 w_eff
__device__ __align__(256) __half g_w1[OQKV*CCH];                // (w_qkv*g) fp16 [o][c] K-major
__device__ __align__(256) __half g_w2[CCH*HID];                 // w_out fp16 [o][he] K-major
__device__ __align__(256) __half g_fT[(size_t)BATCH*HW*CCH];    // feature^T fp16 [b][p][c]
__device__ __align__(256) __half g_kv[(size_t)BATCH*1024*HW];   // k'=exp(k-Mtile) ch 0-511, v'=v*invn 512-1023
__device__ __align__(256) __half g_qs[(size_t)BHN*HW*DH];       // softmaxed q fp16 [bh][p2][d]
__device__ __align__(256) float g_kpm[32*BHN*DH];               // per-tile partial max
__device__ __align__(256) float g_kps[32*BHN*DH];               // per-tile partial sumexp
__device__ __align__(256) float g_kmax[BHN*DH];
__device__ __align__(256) float g_ksum[BHN*DH];
__device__ __align__(256) float g_ctxp[8*BHN*DH*DH];
__device__ __align__(256) float g_ctx[BHN*DH*DH];
__device__ __align__(256) __half g_a3[(size_t)BATCH*HW*HID];    // [b][p][he] fp16 (x 2^18)

// ==================== helpers (sm_80+ PTX, valid on sm_100) ====================
__device__ __forceinline__ uint32_t smem_u32(const void* p) {
    uint32_t a;
    asm("{ .reg .u64 t; cvta.to.shared.u64 t, %1; cvt.u32.u64 %0, t; }" : "=r"(a) : "l"(p));
    return a;
}
__device__ __forceinline__ void ldmx4(uint32_t* r, uint32_t a) {
    asm volatile("ldmatrix.sync.aligned.m8n8.x4.shared.b16 {%0,%1,%2,%3}, [%4];"
        : "=r"(r[0]), "=r"(r[1]), "=r"(r[2]), "=r"(r[3]) : "r"(a));
}
__device__ __forceinline__ void mma_f16(float* d, const uint32_t* a, uint32_t b0, uint32_t b1) {
    asm volatile("mma.sync.aligned.m16n8k16.row.col.f32.f16.f16.f32 "
        "{%0,%1,%2,%3}, {%4,%5,%6,%7}, {%8,%9}, {%0,%1,%2,%3};"
        : "+f"(d[0]), "+f"(d[1]), "+f"(d[2]), "+f"(d[3])
        : "r"(a[0]), "r"(a[1]), "r"(a[2]), "r"(a[3]), "r"(b0), "r"(b1));
}
__device__ __forceinline__ void cp16(uint32_t s, const void* g) {
    asm volatile("cp.async.cg.shared.global [%0], [%1], 16;" :: "r"(s), "l"(g) : "memory");
}
#define CP_COMMIT() asm volatile("cp.async.commit_group;" ::: "memory")
#define CP_WAIT1()  asm volatile("cp.async.wait_group 1;" ::: "memory")
#define CP_WAIT0()  asm volatile("cp.async.wait_group 0;" ::: "memory")

// ==================== weight prep (single fp16) ====================
__global__ void __launch_bounds__(256) prep_w1b(const float* __restrict__ wqkv,
                                                const float* __restrict__ gin) {
    int o = blockIdx.x, c = threadIdx.x;
    float w = wqkv[o*CCH + c] * gin[c];
    __half h = __float2half_rn(w);
    g_w1[o*CCH + c] = h;
    float we = __half2float(h);
    __shared__ float red[256];
    red[c] = we; __syncthreads();
    for (int s = 128; s > 0; s >>= 1) { if (c < s) red[c] += red[c+s]; __syncthreads(); }
    if (c == 0) g_ws[o] = red[0];
}

__global__ void __launch_bounds__(256) prep_w2b(const float* __restrict__ wout) {
    int o = blockIdx.x;
    for (int t = threadIdx.x; t < HID; t += 256)
        g_w2[o*HID + t] = __float2half_rn(wout[o*HID + t]);
}

// ==================== feature transpose + fp16 + LN stats (fused) ====================
__global__ void __launch_bounds__(256) conv_feat(const float* __restrict__ feat) {
    __shared__ float S[128][65];
    __shared__ float s_s[256], s_ss[256];
    int p0 = blockIdx.x*64, b = blockIdx.y;
    int tid = threadIdx.x;
    float sum = 0.f, ssum = 0.f;
    for (int h = 0; h < 2; h++) {
        #pragma unroll
        for (int i = 0; i < 32; i++) {
            int idx = tid + (i<<8);
            int cl = idx >> 6, pl = idx & 63;
            float v = feat[((size_t)(b*CCH + h*128 + cl))*HW + p0 + pl];
            S[cl][pl] = v;
            sum += v; ssum = fmaf(v, v, ssum);
        }
        __syncthreads();
        #pragma unroll
        for (int i = 0; i < 32; i++) {
            int idx = tid + (i<<8);
            int pl = idx >> 7, cl = idx & 127;
            g_fT[((size_t)b*HW + p0 + pl)*CCH + h*128 + cl] = __float2half_rn(S[cl][pl]);
        }
        __syncthreads();
    }
    s_s[tid] = sum; s_ss[tid] = ssum;
    __syncthreads();
    if (tid < 64) {
        float s  = s_s[tid] + s_s[tid+64] + s_s[tid+128] + s_s[tid+192];
        float ss = s_ss[tid] + s_ss[tid+64] + s_ss[tid+128] + s_ss[tid+192];
        float mu = s * (1.f/CCH);
        float var = fmaf(-mu, mu, ss * (1.f/CCH));
        ((float2*)g_stat1)[(size_t)b*HW + p0 + tid] = make_float2(mu, rsqrtf(var + LNEPS));
    }
}

// ==================== warp-MMA GEMM (8 warps, 64x32 tiles, 3-stage, fully unrolled) ====================
// G1=true : TM=128,TN=128,K=256. Epilogue by qkv region (q-softmax / k-exp+partials / v-norm).
// G1=false: TM=256,TN=64, K=512. Epilogue = unscale 2^-18 + full output LN -> d_out.
template<int TM, int TN, int KTOT, bool G1>
__global__ void __launch_bounds__(256, 2) gemm_p(float* __restrict__ Cext,
                                                 const float* __restrict__ gout) {
    extern __shared__ char smem[];
    constexpr int WN     = TN/32;
    constexpr int A_ARR  = TM*SPAD*2;
    constexpr int B_ARR  = TN*SPAD*2;
    constexpr int STAGE  = A_ARR + B_ARR;
    constexpr int BUFB   = TM*(G1 ? (TN+2) : (TN+4))*4;
    constexpr int FIX    = (3*STAGE > BUFB) ? 3*STAGE : BUFB;
    constexpr int KC     = KTOT/32;

    int tid = threadIdx.x, wid = tid >> 5, lane = tid & 31;
    int b = blockIdx.z, m0 = blockIdx.y*TM, n0 = blockIdx.x*TN;
    int wm = wid / WN, wn = wid % WN;
    uint32_t sb = smem_u32(smem);

    const __half* Ap = (G1 ? g_w1 : g_w2) + (size_t)m0*KTOT;
    const __half* Bp = (G1 ? g_fT : g_a3) + ((size_t)b*HW + n0)*KTOT;

    float2* sstat = (float2*)(smem + FIX);          // G1
    float*  sws   = (float*)(smem + FIX + 1024);    // G1
    float*  sg    = (float*)(smem + FIX);           // G4
    float*  ps    = (float*)(smem + FIX + 1024);    // G4
    float*  pss   = (float*)(smem + FIX + 2048);    // G4
    float2* mrs   = (float2*)(smem + FIX + 3072);   // G4

    if (G1) {
        if (tid < 128) sstat[tid] = ((const float2*)g_stat1)[(size_t)b*HW + n0 + tid];
        else           sws[tid-128] = g_ws[m0 + tid - 128];
    } else {
        sg[tid] = gout[tid];
    }

    auto load_stage = [&](int kc, int s) {
        #pragma unroll
        for (int i = 0; i < TM*4/256; i++) {          // A single
            int e = tid + (i << 8);
            int r = e >> 2, q = e & 3;
            cp16(sb + s*STAGE + (r*SPAD + q*8)*2, Ap + (size_t)r*KTOT + kc*32 + q*8);
        }
        #pragma unroll
        for (int i = 0; i < TN*4/256; i++) {          // B single
            int e = tid + (i << 8);
            int r = e >> 2, q = e & 3;
            cp16(sb + s*STAGE + A_ARR + (r*SPAD + q*8)*2, Bp + (size_t)r*KTOT + kc*32 + q*8);
        }
    };

    float acc[4][4][4] = {};
    int lrow = (lane & 7) + (((lane >> 3) & 1) << 3);
    int lcol = (lane >> 4) << 3;

    auto compute_stage = [&](int s) {
        uint32_t sbase = sb + s*STAGE;
        #pragma unroll
        for (int ks = 0; ks < 2; ks++) {
            int kof = ks*16 + lcol;
            uint32_t bf[2][4];
            #pragma unroll
            for (int bt = 0; bt < 2; bt++) {
                int row = wn*32 + bt*16 + lrow;
                ldmx4(bf[bt], sbase + A_ARR + (row*SPAD + kof)*2);
            }
            #pragma unroll
            for (int mt = 0; mt < 4; mt++) {
                uint32_t af[4];
                int row = wm*64 + mt*16 + lrow;
                ldmx4(af, sbase + (row*SPAD + kof)*2);
                #pragma unroll
                for (int nt = 0; nt < 4; nt++) {
                    int bt = nt >> 1, od = nt & 1;
                    mma_f16(acc[mt][nt], af, bf[bt][od], bf[bt][od+2]);
                }
            }
        }
    };

    // 3-stage pipeline, one barrier per chunk; FULLY UNROLLED so all stage
    // offsets (kc%3, (kc+2)%3) fold to immediates — no runtime IMAD chains.
    load_stage(0, 0); CP_COMMIT();
    load_stage(1, 1); CP_COMMIT();
    #pragma unroll
    for (int kc = 0; kc < KC; kc++) {
        if (kc + 1 < KC) { CP_WAIT1(); } else { CP_WAIT0(); }
        __syncthreads();
        if (kc + 2 < KC) {
            load_stage(kc+2, (kc+2) % 3); CP_COMMIT();
        }
        compute_stage(kc % 3);
    }
    __syncthreads();

    if (G1) {
        float* buf = (float*)smem;   // 128 x 128, pitch 130
        #pragma unroll
        for (int mt = 0; mt < 4; mt++) {
            int rml = wm*64 + mt*16 + (lane >> 2);
            #pragma unroll
            for (int nt = 0; nt < 4; nt++) {
                int cl = wn*32 + nt*8 + 2*(lane & 3);
                float* d = acc[mt][nt];
                float2 s0 = sstat[cl], s1 = sstat[cl+1];
                float w0 = sws[rml], w1 = sws[rml+8];
                buf[rml*130 + cl]       = s0.y*(d[0] - s0.x*w0);
                buf[rml*130 + cl + 1]   = s1.y*(d[1] - s1.x*w0);
                buf[(rml+8)*130 + cl]     = s0.y*(d[2] - s0.x*w1);
                buf[(rml+8)*130 + cl + 1] = s1.y*(d[3] - s1.x*w1);
            }
        }
        __syncthreads();
        int region = blockIdx.y >> 2;
        if (region == 0) {
            // q: softmax over d + spatial-transpose store to g_qs (fp16)
            int col = tid & 127, g = tid >> 7;
            int p = n0 + col, h2 = p >> 6, wi = p & 63;
            int bh = b*8 + blockIdx.y*2 + g;
            float mx = -1e30f;
            #pragma unroll 8
            for (int d = 0; d < 64; d++) mx = fmaxf(mx, buf[(g*64+d)*130 + col]);
            float sum = 0.f;
            #pragma unroll 8
            for (int d = 0; d < 64; d++) {
                float e = __expf(buf[(g*64+d)*130 + col] - mx);
                buf[(g*64+d)*130 + col] = e;
                sum += e;
            }
            float r = QSCALE / sum;
            uint4* dst = (uint4*)&g_qs[((size_t)bh*HW + wi*64 + h2)*DH];
            #pragma unroll
            for (int d8 = 0; d8 < 8; d8++) {
                __half2 h0 = __floats2half2_rn(buf[(g*64+d8*8+0)*130+col]*r, buf[(g*64+d8*8+1)*130+col]*r);
                __half2 h1 = __floats2half2_rn(buf[(g*64+d8*8+2)*130+col]*r, buf[(g*64+d8*8+3)*130+col]*r);
                __half2 h2v= __floats2half2_rn(buf[(g*64+d8*8+4)*130+col]*r, buf[(g*64+d8*8+5)*130+col]*r);
                __half2 h3 = __floats2half2_rn(buf[(g*64+d8*8+6)*130+col]*r, buf[(g*64+d8*8+7)*130+col]*r);
                uint4 u;
                u.x = *(uint32_t*)&h0; u.y = *(uint32_t*)&h1;
                u.z = *(uint32_t*)&h2v; u.w = *(uint32_t*)&h3;
                dst[d8] = u;
            }
        } else if (region == 1) {
            // k: per-row tile max, then store exp(k - Mtile) fp16 + online partials
            int row = tid >> 1, half = tid & 1;
            float m = -1e30f;
            #pragma unroll 8
            for (int c = half*64; c < half*64 + 64; c++) m = fmaxf(m, buf[row*130 + c]);
            float om = __shfl_xor_sync(0xffffffffu, m, 1);
            float M = fmaxf(m, om);
            __half2* kvb = (__half2*)(g_kv + ((size_t)(b*1024 + (m0 - 512)))*HW + n0);
            float s = 0.f;
            #pragma unroll 8
            for (int c2 = 0; c2 < 32; c2++) {
                int c = half*64 + 2*c2;
                float e0 = __expf(buf[row*130 + c]     - M);
                float e1 = __expf(buf[row*130 + c + 1] - M);
                s += e0 + e1;
                kvb[(size_t)row*(HW/2) + half*32 + c2] = __floats2half2_rn(e0, e1);
            }
            float os = __shfl_xor_sync(0xffffffffu, s, 1);
            float S = s + os;
            if (half == 0) {
                int ch = (blockIdx.y - 4)*128 + row;
                int r = (b*8 + (ch >> 6))*64 + (ch & 63);
                g_kpm[blockIdx.x*(BHN*DH) + r] = M;
                g_kps[blockIdx.x*(BHN*DH) + r] = S;
            }
        } else {
            // v: per-pixel inverse norm, then store v*invn fp16
            float* sinv2 = (float*)(smem + FIX);  // reuse sstat area (256 floats)
            int col = tid & 127, g = tid >> 7;
            float ss = 0.f;
            #pragma unroll 8
            for (int d = 0; d < 64; d++) {
                float v = buf[(g*64+d)*130 + col];
                ss = fmaf(v, v, ss);
            }
            sinv2[g*128 + col] = 1.f / fmaxf(sqrtf(ss), 1e-12f);
            __syncthreads();
            __half2* kvb = (__half2*)(g_kv + ((size_t)(b*1024 + (m0 - 512)))*HW + n0);
            #pragma unroll 8
            for (int i = 0; i < 32; i++) {
                int idx = tid + (i << 8);
                int row = idx >> 6, c2 = idx & 63;
                int gg = row >> 6;
                float v0 = buf[row*130 + 2*c2]     * sinv2[gg*128 + 2*c2];
                float v1 = buf[row*130 + 2*c2 + 1] * sinv2[gg*128 + 2*c2 + 1];
                kvb[(size_t)row*(HW/2) + c2] = __floats2half2_rn(v0, v1);
            }
        }
    } else {
        // G4 epilogue: unscale a3 factor, then full output LN over 256 channels
        float* buf = (float*)smem;   // 256 x 64, pitch 68
        float* Cb = Cext + ((size_t)(b*CCH + m0))*HW + n0;
        #pragma unroll
        for (int mt = 0; mt < 4; mt++) {
            int rml = wm*64 + mt*16 + (lane >> 2);
            #pragma unroll
            for (int nt = 0; nt < 4; nt++) {
                int cl = wn*32 + nt*8 + 2*(lane & 3);
                float* d = acc[mt][nt];
                buf[rml*68 + cl]     = d[0] * A3UNSCALE;
                buf[rml*68 + cl + 1] = d[1] * A3UNSCALE;
                buf[(rml+8)*68 + cl]     = d[2] * A3UNSCALE;
                buf[(rml+8)*68 + cl + 1] = d[3] * A3UNSCALE;
            }
        }
        __syncthreads();
        {
            int col = tid & 63, part = tid >> 6;
            float s = 0.f, ss = 0.f;
            #pragma unroll 8
            for (int r = part*64; r < part*64 + 64; r++) {
                float v = buf[r*68 + col];
                s += v; ss = fmaf(v, v, ss);
            }
            ps[part*64 + col] = s;
            pss[part*64 + col] = ss;
        }
        __syncthreads();
        if (tid < 64) {
            float s  = ps[tid] + ps[64+tid] + ps[128+tid] + ps[192+tid];
            float ss = pss[tid] + pss[64+tid] + pss[128+tid] + pss[192+tid];
            float mu = s * (1.f/CCH);
            float var = fmaf(-mu, mu, ss * (1.f/CCH));
            mrs[tid] = make_float2(mu, rsqrtf(var + LNEPS));
        }
        __syncthreads();
        #pragma unroll 8
        for (int i = 0; i < 64; i++) {
            int idx = tid + (i << 8);
            int row = idx >> 6, col = idx & 63;
            float2 st = mrs[col];
            Cb[(size_t)row*HW + col] = (buf[row*68 + col] - st.x) * st.y * sg[row];
        }
    }
}

// ==================== merge k-softmax partials over 32 tiles ====================
__global__ void __launch_bounds__(256) kmerge() {
    int r = blockIdx.x*8 + (threadIdx.x >> 5);
    int lane = threadIdx.x & 31;
    float m = g_kpm[lane*(BHN*DH) + r];
    float s = g_kps[lane*(BHN*DH) + r];
    float M = m;
    #pragma unroll
    for (int o = 16; o > 0; o >>= 1) M = fmaxf(M, __shfl_xor_sync(0xffffffffu, M, o));
    float sc = s * __expf(m - M);
    #pragma unroll
    for (int o = 16; o > 0; o >>= 1) sc += __shfl_xor_sync(0xffffffffu, sc, o);
    if (lane == 0) { g_kmax[r] = M; g_ksum[r] = sc; }
}

// ==================== context partials: tensor-core MMA over exp'd k / scaled v ====================
#define G2PITCH 136
#define G2TILE  (64*G2PITCH*2)    /* 17408 B per operand tile */
#define G2STG   (2*G2TILE)        /* 34816 B per stage */
#define SMEM_G2 (2*G2STG)         /* 69632 B */

__global__ void __launch_bounds__(256, 2) gemm2() {
    extern __shared__ char smem[];
    uint32_t sb = smem_u32(smem);
    int sp = blockIdx.x, bh = blockIdx.y;
    int b = bh >> 3, head = bh & 7;
    int tid = threadIdx.x, wid = tid >> 5, lane = tid & 31;
    int wm = wid >> 1, wn = wid & 1;
    const __half* kbase = g_kv + ((size_t)(b*1024 + head*DH))*HW;
    const __half* vbase = g_kv + ((size_t)(b*1024 + 512 + head*DH))*HW;
    int n0 = sp*512;

    int r0 = wm*16 + (lane >> 2), r1 = r0 + 8;
    float km0 = g_kmax[bh*64 + r0], km1 = g_kmax[bh*64 + r1];
    float rs0 = 1.f / g_ksum[bh*64 + r0], rs1 = 1.f / g_ksum[bh*64 + r1];

    auto load_blk = [&](int blk, int s) {
        int nb = n0 + blk*128;
        #pragma unroll
        for (int i = 0; i < 8; i++) {
            int e = tid + (i << 8);
            int isv = e >= 1024;
            int rq = e & 1023;
            int r = rq >> 4, q = rq & 15;
            const __half* src = (isv ? vbase : kbase) + (size_t)r*HW + nb + q*8;
            cp16(sb + s*G2STG + isv*G2TILE + (r*G2PITCH + q*8)*2, src);
        }
    };

    float accT[4][4] = {};
    int lrow = (lane & 7) + (((lane >> 3) & 1) << 3);
    int lcol = (lane >> 4) << 3;

    load_blk(0, 0); CP_COMMIT();
    #pragma unroll
    for (int blk = 0; blk < 4; blk++) {
        if (blk + 1 < 4) { load_blk(blk+1, (blk+1) & 1); }
        CP_COMMIT();
        if (blk + 1 < 4) { CP_WAIT1(); } else { CP_WAIT0(); }
        __syncthreads();
        uint32_t base = sb + (blk & 1)*G2STG;
        float accB[4][4] = {};
        #pragma unroll
        for (int ks = 0; ks < 8; ks++) {
            int kof = ks*16 + lcol;
            uint32_t af[4];
            {
                int row = wm*16 + lrow;
                ldmx4(af, base + (row*G2PITCH + kof)*2);
            }
            uint32_t bf[2][4];
            #pragma unroll
            for (int bt = 0; bt < 2; bt++) {
                int row = wn*32 + bt*16 + lrow;
                ldmx4(bf[bt], base + G2TILE + (row*G2PITCH + kof)*2);
            }
            #pragma unroll
            for (int nt = 0; nt < 4; nt++) {
                int bt = nt >> 1, od = nt & 1;
                mma_f16(accB[nt], af, bf[bt][od], bf[bt][od+2]);
            }
        }
        int tile = sp*4 + blk;
        float sc0 = __expf(g_kpm[(size_t)tile*(BHN*DH) + bh*64 + r0] - km0) * rs0;
        float sc1 = __expf(g_kpm[(size_t)tile*(BHN*DH) + bh*64 + r1] - km1) * rs1;
        #pragma unroll
        for (int nt = 0; nt < 4; nt++) {
            accT[nt][0] = fmaf(sc0, accB[nt][0], accT[nt][0]);
            accT[nt][1] = fmaf(sc0, accB[nt][1], accT[nt][1]);
            accT[nt][2] = fmaf(sc1, accB[nt][2], accT[nt][2]);
            accT[nt][3] = fmaf(sc1, accB[nt][3], accT[nt][3]);
        }
        __syncthreads();
    }
    float* cp = g_ctxp + ((size_t)(sp*BHN + bh))*4096;
    #pragma unroll
    for (int nt = 0; nt < 4; nt++) {
        int cl = wn*32 + nt*8 + 2*(lane & 3);
        *(float2*)&cp[r0*64 + cl] = make_float2(accT[nt][0], accT[nt][1]);
        *(float2*)&cp[r1*64 + cl] = make_float2(accT[nt][2], accT[nt][3]);
    }
}

__global__ void __launch_bounds__(256) ctxred() {
    int bh = blockIdx.x, tid = threadIdx.x;
    for (int i = tid; i < 4096; i += 256) {
        float s = 0.f;
        #pragma unroll
        for (int sp = 0; sp < 8; sp++) s += g_ctxp[((size_t)(sp*BHN + bh))*4096 + i];
        g_ctx[(size_t)bh*4096 + i] = s * INV_N;
    }
}

// ==================== out = qs @ ctx -> a3 fp16 (x 2^18) [b][p][he] ====================
__global__ void __launch_bounds__(256) gemm3() {
    __shared__ float Cs[64][64];
    __shared__ float Qs[64][65];
    int p2t = blockIdx.x, bh = blockIdx.y;
    int b = bh >> 3, head = bh & 7;
    int tid = threadIdx.x;
    const float* ctx = g_ctx + (size_t)bh*4096;
    for (int i = tid; i < 4096; i += 256) Cs[i>>6][i&63] = ctx[i];
    const uint2* qb = (const uint2*)(g_qs + ((size_t)bh*HW + p2t*64)*DH);
    #pragma unroll
    for (int i = 0; i < 4; i++) {
        int idx = tid + (i<<8);
        uint2 raw = qb[idx];
        float2 a = __half22float2(*(__half2*)&raw.x);
        float2 c = __half22float2(*(__half2*)&raw.y);
        int lin = idx << 2;
        int row = lin >> 6, col = lin & 63;
        Qs[row][col]   = a.x; Qs[row][col+1] = a.y;
        Qs[row][col+2] = c.x; Qs[row][col+3] = c.y;
    }
    __syncthreads();
    int tx = tid & 15, ty = tid >> 4;
    float acc[4][4] = {};
    #pragma unroll
    for (int d = 0; d < 64; d++) {
        float a0 = Qs[(ty<<2)+0][d], a1 = Qs[(ty<<2)+1][d];
        float a2 = Qs[(ty<<2)+2][d], a3 = Qs[(ty<<2)+3][d];
        float4 bv = *(float4*)&Cs[d][tx<<2];
        acc[0][0]+=a0*bv.x; acc[0][1]+=a0*bv.y; acc[0][2]+=a0*bv.z; acc[0][3]+=a0*bv.w;
        acc[1][0]+=a1*bv.x; acc[1][1]+=a1*bv.y; acc[1][2]+=a1*bv.z; acc[1][3]+=a1*bv.w;
        acc[2][0]+=a2*bv.x; acc[2][1]+=a2*bv.y; acc[2][2]+=a2*bv.z; acc[2][3]+=a2*bv.w;
        acc[3][0]+=a3*bv.x; acc[3][1]+=a3*bv.y; acc[3][2]+=a3*bv.z; acc[3][3]+=a3*bv.w;
    }
    __syncthreads();
    #pragma unroll
    for (int i = 0; i < 4; i++)
        #pragma unroll
        for (int j = 0; j < 4; j++)
            Qs[(ty<<2)+i][(tx<<2)+j] = acc[i][j];   // [p2l][e]
    __syncthreads();
    size_t rowbase = (size_t)b*HW + p2t*64;
    #pragma unroll
    for (int i = 0; i < 16; i++) {
        int idx = tid + (i<<8); int pl = idx >> 6, e = idx & 63;
        g_a3[(rowbase + pl)*HID + head*DH + e] = __float2half_rn(Qs[pl][e] * A3SCALE);
    }
}

// ==================== launch ====================
#define SMEM_G1 68096    /* max(3*20480=61440, 128*130*4=66560) + 1536 */
#define SMEM_G4 80384    /* max(3*25600=76800, 256*68*4=69632)  + 3584 */

extern "C" void kernel_launch(void* const* d_in, const int* in_sizes, int n_in,
                              void* d_out, int out_size) {
    const float* feat = (const float*)d_in[0];
    const float* gin  = (const float*)d_in[1];
    const float* wqkv = (const float*)d_in[2];
    const float* wout = (const float*)d_in[3];
    const float* gout = (const float*)d_in[4];
    float* out = (float*)d_out;

    cudaFuncSetAttribute(gemm_p<128,128,256,true>,
                         cudaFuncAttributeMaxDynamicSharedMemorySize, SMEM_G1);
    cudaFuncSetAttribute(gemm_p<256,64,512,false>,
                         cudaFuncAttributeMaxDynamicSharedMemorySize, SMEM_G4);
    cudaFuncSetAttribute(gemm2,
                         cudaFuncAttributeMaxDynamicSharedMemorySize, SMEM_G2);

    prep_w1b<<<OQKV, 256>>>(wqkv, gin);
    prep_w2b<<<CCH, 256>>>(wout);
    conv_feat<<<dim3(HW/64, BATCH), 256>>>(feat);
    gemm_p<128,128,256,true><<<dim3(HW/128, OQKV/128, BATCH), 256, SMEM_G1>>>(nullptr, nullptr);
    kmerge<<<BHN*DH/8, 256>>>();
    gemm2<<<dim3(8, BHN), 256, SMEM_G2>>>();
    ctxred<<<BHN, 256>>>();
    gemm3<<<dim3(HW/64, BHN), 256>>>();
    gemm_p<256,64,512,false><<<dim3(HW/64, 1, BATCH), 256, SMEM_G4>>>(out, gout);
}

// round 14
// speedup vs baseline: 1.3105x; 1.2551x over previous
#include <cuda_runtime.h>
#include <cuda_fp16.h>
#include <math.h>
#include <stdint.h>

#define BATCH 16
#define CCH   256
#define HW    4096
#define HEADS 8
#define DH    64
#define HID   512
#define OQKV  1536
#define BHN   (BATCH*HEADS)   /* 128 */
#define QSCALE 0.125f
#define LNEPS  1e-5f
#define INV_N  (1.0f/4096.0f)
#define SPAD  40   /* smem row pitch in fp16: 80B -> 8 ldmatrix rows hit distinct banks */
// a3 = (qs @ ctx_noInvN) * A3SCALE; ctx_noInvN carries no 1/N, so A3SCALE = 2^18/4096 = 64
// keeps stored a3 numerically identical to previous rounds. G4 unscale = 1/2^18 as before.
#define A3SCALE    64.0f
#define A3UNSCALE  (1.0f/262144.0f)

// ==================== scratch (device globals; no allocations) ====================
__device__ __align__(256) float g_stat1[BATCH*HW*2];            // (mu, rstd) input LN
__device__ __align__(256) float g_ws[OQKV];                     // row sums of fp16 w_eff
__device__ __align__(256) __half g_w1[OQKV*CCH];                // (w_qkv*g) fp16 [o][c] K-major
__device__ __align__(256) __half g_w2[CCH*HID];                 // w_out fp16 [o][he] K-major
__device__ __align__(256) __half g_fT[(size_t)BATCH*HW*CCH];    // feature^T fp16 [b][p][c]
__device__ __align__(256) __half g_kv[(size_t)BATCH*1024*HW];   // k'=exp(k-Mtile) ch 0-511, v'=v*invn 512-1023
__device__ __align__(256) __half g_qs[(size_t)BHN*HW*DH];       // softmaxed q fp16 [bh][p2][d]
__device__ __align__(256) float g_kpm[32*BHN*DH];               // per-tile partial max
__device__ __align__(256) float g_kps[32*BHN*DH];               // per-tile partial sumexp
__device__ __align__(256) float g_kmax[BHN*DH];
__device__ __align__(256) float g_ksum[BHN*DH];
__device__ __align__(256) float g_ctxp[8*BHN*DH*DH];
__device__ __align__(256) __half g_ctxT[BHN*DH*DH];             // ctx^T fp16 [bh][e][d], NO 1/N
__device__ __align__(256) __half g_a3[(size_t)BATCH*HW*HID];    // [b][p][he] fp16 (x 2^18 effective)

// ==================== helpers (sm_80+ PTX, valid on sm_100) ====================
__device__ __forceinline__ uint32_t smem_u32(const void* p) {
    uint32_t a;
    asm("{ .reg .u64 t; cvta.to.shared.u64 t, %1; cvt.u32.u64 %0, t; }" : "=r"(a) : "l"(p));
    return a;
}
__device__ __forceinline__ void ldmx4(uint32_t* r, uint32_t a) {
    asm volatile("ldmatrix.sync.aligned.m8n8.x4.shared.b16 {%0,%1,%2,%3}, [%4];"
        : "=r"(r[0]), "=r"(r[1]), "=r"(r[2]), "=r"(r[3]) : "r"(a));
}
__device__ __forceinline__ void mma_f16(float* d, const uint32_t* a, uint32_t b0, uint32_t b1) {
    asm volatile("mma.sync.aligned.m16n8k16.row.col.f32.f16.f16.f32 "
        "{%0,%1,%2,%3}, {%4,%5,%6,%7}, {%8,%9}, {%0,%1,%2,%3};"
        : "+f"(d[0]), "+f"(d[1]), "+f"(d[2]), "+f"(d[3])
        : "r"(a[0]), "r"(a[1]), "r"(a[2]), "r"(a[3]), "r"(b0), "r"(b1));
}
__device__ __forceinline__ void cp16(uint32_t s, const void* g) {
    asm volatile("cp.async.cg.shared.global [%0], [%1], 16;" :: "r"(s), "l"(g) : "memory");
}
#define CP_COMMIT() asm volatile("cp.async.commit_group;" ::: "memory")
#define CP_WAIT1()  asm volatile("cp.async.wait_group 1;" ::: "memory")
#define CP_WAIT0()  asm volatile("cp.async.wait_group 0;" ::: "memory")

// ==================== weight prep (single fp16) ====================
__global__ void __launch_bounds__(256) prep_w1b(const float* __restrict__ wqkv,
                                                const float* __restrict__ gin) {
    int o = blockIdx.x, c = threadIdx.x;
    float w = wqkv[o*CCH + c] * gin[c];
    __half h = __float2half_rn(w);
    g_w1[o*CCH + c] = h;
    float we = __half2float(h);
    __shared__ float red[256];
    red[c] = we; __syncthreads();
    for (int s = 128; s > 0; s >>= 1) { if (c < s) red[c] += red[c+s]; __syncthreads(); }
    if (c == 0) g_ws[o] = red[0];
}

__global__ void __launch_bounds__(256) prep_w2b(const float* __restrict__ wout) {
    int o = blockIdx.x;
    for (int t = threadIdx.x; t < HID; t += 256)
        g_w2[o*HID + t] = __float2half_rn(wout[o*HID + t]);
}

// ==================== feature transpose + fp16 + LN stats (fused) ====================
__global__ void __launch_bounds__(256) conv_feat(const float* __restrict__ feat) {
    __shared__ float S[128][65];
    __shared__ float s_s[256], s_ss[256];
    int p0 = blockIdx.x*64, b = blockIdx.y;
    int tid = threadIdx.x;
    float sum = 0.f, ssum = 0.f;
    for (int h = 0; h < 2; h++) {
        #pragma unroll
        for (int i = 0; i < 32; i++) {
            int idx = tid + (i<<8);
            int cl = idx >> 6, pl = idx & 63;
            float v = feat[((size_t)(b*CCH + h*128 + cl))*HW + p0 + pl];
            S[cl][pl] = v;
            sum += v; ssum = fmaf(v, v, ssum);
        }
        __syncthreads();
        #pragma unroll
        for (int i = 0; i < 32; i++) {
            int idx = tid + (i<<8);
            int pl = idx >> 7, cl = idx & 127;
            g_fT[((size_t)b*HW + p0 + pl)*CCH + h*128 + cl] = __float2half_rn(S[cl][pl]);
        }
        __syncthreads();
    }
    s_s[tid] = sum; s_ss[tid] = ssum;
    __syncthreads();
    if (tid < 64) {
        float s  = s_s[tid] + s_s[tid+64] + s_s[tid+128] + s_s[tid+192];
        float ss = s_ss[tid] + s_ss[tid+64] + s_ss[tid+128] + s_ss[tid+192];
        float mu = s * (1.f/CCH);
        float var = fmaf(-mu, mu, ss * (1.f/CCH));
        ((float2*)g_stat1)[(size_t)b*HW + p0 + tid] = make_float2(mu, rsqrtf(var + LNEPS));
    }
}

// ==================== warp-MMA GEMM (8 warps, 64x32 tiles, 3-stage, fully unrolled) ====================
// G1=true : TM=128,TN=128,K=256. Epilogue by qkv region (q-softmax / k-exp+partials / v-norm).
// G1=false: TM=256,TN=64, K=512. Epilogue = unscale 2^-18 + full output LN -> d_out.
template<int TM, int TN, int KTOT, bool G1>
__global__ void __launch_bounds__(256, 2) gemm_p(float* __restrict__ Cext,
                                                 const float* __restrict__ gout) {
    extern __shared__ char smem[];
    constexpr int WN     = TN/32;
    constexpr int A_ARR  = TM*SPAD*2;
    constexpr int B_ARR  = TN*SPAD*2;
    constexpr int STAGE  = A_ARR + B_ARR;
    constexpr int BUFB   = TM*(G1 ? (TN+2) : (TN+4))*4;
    constexpr int FIX    = (3*STAGE > BUFB) ? 3*STAGE : BUFB;
    constexpr int KC     = KTOT/32;

    int tid = threadIdx.x, wid = tid >> 5, lane = tid & 31;
    int b = blockIdx.z, m0 = blockIdx.y*TM, n0 = blockIdx.x*TN;
    int wm = wid / WN, wn = wid % WN;
    uint32_t sb = smem_u32(smem);

    const __half* Ap = (G1 ? g_w1 : g_w2) + (size_t)m0*KTOT;
    const __half* Bp = (G1 ? g_fT : g_a3) + ((size_t)b*HW + n0)*KTOT;

    float2* sstat = (float2*)(smem + FIX);          // G1
    float*  sws   = (float*)(smem + FIX + 1024);    // G1
    float*  sg    = (float*)(smem + FIX);           // G4
    float*  ps    = (float*)(smem + FIX + 1024);    // G4
    float*  pss   = (float*)(smem + FIX + 2048);    // G4
    float2* mrs   = (float2*)(smem + FIX + 3072);   // G4

    if (G1) {
        if (tid < 128) sstat[tid] = ((const float2*)g_stat1)[(size_t)b*HW + n0 + tid];
        else           sws[tid-128] = g_ws[m0 + tid - 128];
    } else {
        sg[tid] = gout[tid];
    }

    auto load_stage = [&](int kc, int s) {
        #pragma unroll
        for (int i = 0; i < TM*4/256; i++) {          // A single
            int e = tid + (i << 8);
            int r = e >> 2, q = e & 3;
            cp16(sb + s*STAGE + (r*SPAD + q*8)*2, Ap + (size_t)r*KTOT + kc*32 + q*8);
        }
        #pragma unroll
        for (int i = 0; i < TN*4/256; i++) {          // B single
            int e = tid + (i << 8);
            int r = e >> 2, q = e & 3;
            cp16(sb + s*STAGE + A_ARR + (r*SPAD + q*8)*2, Bp + (size_t)r*KTOT + kc*32 + q*8);
        }
    };

    float acc[4][4][4] = {};
    int lrow = (lane & 7) + (((lane >> 3) & 1) << 3);
    int lcol = (lane >> 4) << 3;

    auto compute_stage = [&](int s) {
        uint32_t sbase = sb + s*STAGE;
        #pragma unroll
        for (int ks = 0; ks < 2; ks++) {
            int kof = ks*16 + lcol;
            uint32_t bf[2][4];
            #pragma unroll
            for (int bt = 0; bt < 2; bt++) {
                int row = wn*32 + bt*16 + lrow;
                ldmx4(bf[bt], sbase + A_ARR + (row*SPAD + kof)*2);
            }
            #pragma unroll
            for (int mt = 0; mt < 4; mt++) {
                uint32_t af[4];
                int row = wm*64 + mt*16 + lrow;
                ldmx4(af, sbase + (row*SPAD + kof)*2);
                #pragma unroll
                for (int nt = 0; nt < 4; nt++) {
                    int bt = nt >> 1, od = nt & 1;
                    mma_f16(acc[mt][nt], af, bf[bt][od], bf[bt][od+2]);
                }
            }
        }
    };

    // 3-stage pipeline, one barrier per chunk; fully unrolled stage indices
    load_stage(0, 0); CP_COMMIT();
    load_stage(1, 1); CP_COMMIT();
    #pragma unroll
    for (int kc = 0; kc < KC; kc++) {
        if (kc + 1 < KC) { CP_WAIT1(); } else { CP_WAIT0(); }
        __syncthreads();
        if (kc + 2 < KC) {
            load_stage(kc+2, (kc+2) % 3); CP_COMMIT();
        }
        compute_stage(kc % 3);
    }
    __syncthreads();

    if (G1) {
        float* buf = (float*)smem;   // 128 x 128, pitch 130
        #pragma unroll
        for (int mt = 0; mt < 4; mt++) {
            int rml = wm*64 + mt*16 + (lane >> 2);
            #pragma unroll
            for (int nt = 0; nt < 4; nt++) {
                int cl = wn*32 + nt*8 + 2*(lane & 3);
                float* d = acc[mt][nt];
                float2 s0 = sstat[cl], s1 = sstat[cl+1];
                float w0 = sws[rml], w1 = sws[rml+8];
                buf[rml*130 + cl]       = s0.y*(d[0] - s0.x*w0);
                buf[rml*130 + cl + 1]   = s1.y*(d[1] - s1.x*w0);
                buf[(rml+8)*130 + cl]     = s0.y*(d[2] - s0.x*w1);
                buf[(rml+8)*130 + cl + 1] = s1.y*(d[3] - s1.x*w1);
            }
        }
        __syncthreads();
        int region = blockIdx.y >> 2;
        if (region == 0) {
            // q: softmax over d + spatial-transpose store to g_qs (fp16)
            int col = tid & 127, g = tid >> 7;
            int p = n0 + col, h2 = p >> 6, wi = p & 63;
            int bh = b*8 + blockIdx.y*2 + g;
            float mx = -1e30f;
            #pragma unroll 8
            for (int d = 0; d < 64; d++) mx = fmaxf(mx, buf[(g*64+d)*130 + col]);
            float sum = 0.f;
            #pragma unroll 8
            for (int d = 0; d < 64; d++) {
                float e = __expf(buf[(g*64+d)*130 + col] - mx);
                buf[(g*64+d)*130 + col] = e;
                sum += e;
            }
            float r = QSCALE / sum;
            uint4* dst = (uint4*)&g_qs[((size_t)bh*HW + wi*64 + h2)*DH];
            #pragma unroll
            for (int d8 = 0; d8 < 8; d8++) {
                __half2 h0 = __floats2half2_rn(buf[(g*64+d8*8+0)*130+col]*r, buf[(g*64+d8*8+1)*130+col]*r);
                __half2 h1 = __floats2half2_rn(buf[(g*64+d8*8+2)*130+col]*r, buf[(g*64+d8*8+3)*130+col]*r);
                __half2 h2v= __floats2half2_rn(buf[(g*64+d8*8+4)*130+col]*r, buf[(g*64+d8*8+5)*130+col]*r);
                __half2 h3 = __floats2half2_rn(buf[(g*64+d8*8+6)*130+col]*r, buf[(g*64+d8*8+7)*130+col]*r);
                uint4 u;
                u.x = *(uint32_t*)&h0; u.y = *(uint32_t*)&h1;
                u.z = *(uint32_t*)&h2v; u.w = *(uint32_t*)&h3;
                dst[d8] = u;
            }
        } else if (region == 1) {
            // k: per-row tile max, then store exp(k - Mtile) fp16 + online partials
            int row = tid >> 1, half = tid & 1;
            float m = -1e30f;
            #pragma unroll 8
            for (int c = half*64; c < half*64 + 64; c++) m = fmaxf(m, buf[row*130 + c]);
            float om = __shfl_xor_sync(0xffffffffu, m, 1);
            float M = fmaxf(m, om);
            __half2* kvb = (__half2*)(g_kv + ((size_t)(b*1024 + (m0 - 512)))*HW + n0);
            float s = 0.f;
            #pragma unroll 8
            for (int c2 = 0; c2 < 32; c2++) {
                int c = half*64 + 2*c2;
                float e0 = __expf(buf[row*130 + c]     - M);
                float e1 = __expf(buf[row*130 + c + 1] - M);
                s += e0 + e1;
                kvb[(size_t)row*(HW/2) + half*32 + c2] = __floats2half2_rn(e0, e1);
            }
            float os = __shfl_xor_sync(0xffffffffu, s, 1);
            float S = s + os;
            if (half == 0) {
                int ch = (blockIdx.y - 4)*128 + row;
                int r = (b*8 + (ch >> 6))*64 + (ch & 63);
                g_kpm[blockIdx.x*(BHN*DH) + r] = M;
                g_kps[blockIdx.x*(BHN*DH) + r] = S;
            }
        } else {
            // v: per-pixel inverse norm, then store v*invn fp16
            float* sinv2 = (float*)(smem + FIX);  // reuse sstat area (256 floats)
            int col = tid & 127, g = tid >> 7;
            float ss = 0.f;
            #pragma unroll 8
            for (int d = 0; d < 64; d++) {
                float v = buf[(g*64+d)*130 + col];
                ss = fmaf(v, v, ss);
            }
            sinv2[g*128 + col] = 1.f / fmaxf(sqrtf(ss), 1e-12f);
            __syncthreads();
            __half2* kvb = (__half2*)(g_kv + ((size_t)(b*1024 + (m0 - 512)))*HW + n0);
            #pragma unroll 8
            for (int i = 0; i < 32; i++) {
                int idx = tid + (i << 8);
                int row = idx >> 6, c2 = idx & 63;
                int gg = row >> 6;
                float v0 = buf[row*130 + 2*c2]     * sinv2[gg*128 + 2*c2];
                float v1 = buf[row*130 + 2*c2 + 1] * sinv2[gg*128 + 2*c2 + 1];
                kvb[(size_t)row*(HW/2) + c2] = __floats2half2_rn(v0, v1);
            }
        }
    } else {
        // G4 epilogue: unscale a3 factor, then full output LN over 256 channels
        float* buf = (float*)smem;   // 256 x 64, pitch 68
        float* Cb = Cext + ((size_t)(b*CCH + m0))*HW + n0;
        #pragma unroll
        for (int mt = 0; mt < 4; mt++) {
            int rml = wm*64 + mt*16 + (lane >> 2);
            #pragma unroll
            for (int nt = 0; nt < 4; nt++) {
                int cl = wn*32 + nt*8 + 2*(lane & 3);
                float* d = acc[mt][nt];
                buf[rml*68 + cl]     = d[0] * A3UNSCALE;
                buf[rml*68 + cl + 1] = d[1] * A3UNSCALE;
                buf[(rml+8)*68 + cl]     = d[2] * A3UNSCALE;
                buf[(rml+8)*68 + cl + 1] = d[3] * A3UNSCALE;
            }
        }
        __syncthreads();
        {
            int col = tid & 63, part = tid >> 6;
            float s = 0.f, ss = 0.f;
            #pragma unroll 8
            for (int r = part*64; r < part*64 + 64; r++) {
                float v = buf[r*68 + col];
                s += v; ss = fmaf(v, v, ss);
            }
            ps[part*64 + col] = s;
            pss[part*64 + col] = ss;
        }
        __syncthreads();
        if (tid < 64) {
            float s  = ps[tid] + ps[64+tid] + ps[128+tid] + ps[192+tid];
            float ss = pss[tid] + pss[64+tid] + pss[128+tid] + pss[192+tid];
            float mu = s * (1.f/CCH);
            float var = fmaf(-mu, mu, ss * (1.f/CCH));
            mrs[tid] = make_float2(mu, rsqrtf(var + LNEPS));
        }
        __syncthreads();
        #pragma unroll 8
        for (int i = 0; i < 64; i++) {
            int idx = tid + (i << 8);
            int row = idx >> 6, col = idx & 63;
            float2 st = mrs[col];
            Cb[(size_t)row*HW + col] = (buf[row*68 + col] - st.x) * st.y * sg[row];
        }
    }
}

// ==================== merge k-softmax partials over 32 tiles ====================
__global__ void __launch_bounds__(256) kmerge() {
    int r = blockIdx.x*8 + (threadIdx.x >> 5);
    int lane = threadIdx.x & 31;
    float m = g_kpm[lane*(BHN*DH) + r];
    float s = g_kps[lane*(BHN*DH) + r];
    float M = m;
    #pragma unroll
    for (int o = 16; o > 0; o >>= 1) M = fmaxf(M, __shfl_xor_sync(0xffffffffu, M, o));
    float sc = s * __expf(m - M);
    #pragma unroll
    for (int o = 16; o > 0; o >>= 1) sc += __shfl_xor_sync(0xffffffffu, sc, o);
    if (lane == 0) { g_kmax[r] = M; g_ksum[r] = sc; }
}

// ==================== context partials: tensor-core MMA over exp'd k / scaled v ====================
#define G2PITCH 136
#define G2TILE  (64*G2PITCH*2)    /* 17408 B per operand tile */
#define G2STG   (2*G2TILE)        /* 34816 B per stage */
#define SMEM_G2 (2*G2STG)         /* 69632 B */

__global__ void __launch_bounds__(256, 2) gemm2() {
    extern __shared__ char smem[];
    uint32_t sb = smem_u32(smem);
    int sp = blockIdx.x, bh = blockIdx.y;
    int b = bh >> 3, head = bh & 7;
    int tid = threadIdx.x, wid = tid >> 5, lane = tid & 31;
    int wm = wid >> 1, wn = wid & 1;
    const __half* kbase = g_kv + ((size_t)(b*1024 + head*DH))*HW;
    const __half* vbase = g_kv + ((size_t)(b*1024 + 512 + head*DH))*HW;
    int n0 = sp*512;

    int r0 = wm*16 + (lane >> 2), r1 = r0 + 8;
    float km0 = g_kmax[bh*64 + r0], km1 = g_kmax[bh*64 + r1];
    float rs0 = 1.f / g_ksum[bh*64 + r0], rs1 = 1.f / g_ksum[bh*64 + r1];

    auto load_blk = [&](int blk, int s) {
        int nb = n0 + blk*128;
        #pragma unroll
        for (int i = 0; i < 8; i++) {
            int e = tid + (i << 8);
            int isv = e >= 1024;
            int rq = e & 1023;
            int r = rq >> 4, q = rq & 15;
            const __half* src = (isv ? vbase : kbase) + (size_t)r*HW + nb + q*8;
            cp16(sb + s*G2STG + isv*G2TILE + (r*G2PITCH + q*8)*2, src);
        }
    };

    float accT[4][4] = {};
    int lrow = (lane & 7) + (((lane >> 3) & 1) << 3);
    int lcol = (lane >> 4) << 3;

    load_blk(0, 0); CP_COMMIT();
    #pragma unroll
    for (int blk = 0; blk < 4; blk++) {
        if (blk + 1 < 4) { load_blk(blk+1, (blk+1) & 1); }
        CP_COMMIT();
        if (blk + 1 < 4) { CP_WAIT1(); } else { CP_WAIT0(); }
        __syncthreads();
        uint32_t base = sb + (blk & 1)*G2STG;
        float accB[4][4] = {};
        #pragma unroll
        for (int ks = 0; ks < 8; ks++) {
            int kof = ks*16 + lcol;
            uint32_t af[4];
            {
                int row = wm*16 + lrow;
                ldmx4(af, base + (row*G2PITCH + kof)*2);
            }
            uint32_t bf[2][4];
            #pragma unroll
            for (int bt = 0; bt < 2; bt++) {
                int row = wn*32 + bt*16 + lrow;
                ldmx4(bf[bt], base + G2TILE + (row*G2PITCH + kof)*2);
            }
            #pragma unroll
            for (int nt = 0; nt < 4; nt++) {
                int bt = nt >> 1, od = nt & 1;
                mma_f16(accB[nt], af, bf[bt][od], bf[bt][od+2]);
            }
        }
        int tile = sp*4 + blk;
        float sc0 = __expf(g_kpm[(size_t)tile*(BHN*DH) + bh*64 + r0] - km0) * rs0;
        float sc1 = __expf(g_kpm[(size_t)tile*(BHN*DH) + bh*64 + r1] - km1) * rs1;
        #pragma unroll
        for (int nt = 0; nt < 4; nt++) {
            accT[nt][0] = fmaf(sc0, accB[nt][0], accT[nt][0]);
            accT[nt][1] = fmaf(sc0, accB[nt][1], accT[nt][1]);
            accT[nt][2] = fmaf(sc1, accB[nt][2], accT[nt][2]);
            accT[nt][3] = fmaf(sc1, accB[nt][3], accT[nt][3]);
        }
        __syncthreads();
    }
    float* cp = g_ctxp + ((size_t)(sp*BHN + bh))*4096;
    #pragma unroll
    for (int nt = 0; nt < 4; nt++) {
        int cl = wn*32 + nt*8 + 2*(lane & 3);
        *(float2*)&cp[r0*64 + cl] = make_float2(accT[nt][0], accT[nt][1]);
        *(float2*)&cp[r1*64 + cl] = make_float2(accT[nt][2], accT[nt][3]);
    }
}

// ==================== reduce split-K partials, transpose, fp16 (NO 1/N) ====================
__global__ void __launch_bounds__(256) ctxred() {
    __shared__ float T[64][65];
    int bh = blockIdx.x, tid = threadIdx.x;
    for (int i = tid; i < 4096; i += 256) {
        float s = 0.f;
        #pragma unroll
        for (int sp = 0; sp < 8; sp++) s += g_ctxp[((size_t)(sp*BHN + bh))*4096 + i];
        T[i >> 6][i & 63] = s;                      // T[d][e]
    }
    __syncthreads();
    for (int i = tid; i < 4096; i += 256) {
        int e = i >> 6, d = i & 63;
        g_ctxT[(size_t)bh*4096 + i] = __float2half_rn(T[d][e]);   // [e][d]
    }
}

// ==================== gemm3 (tensor-core): a3 = (qs @ ctx^T^T) * A3SCALE -> fp16 ====================
#define G3PITCH 72   /* 144B row pitch: 8 consecutive rows hit distinct 16B banks */
__global__ void __launch_bounds__(256) gemm3() {
    __shared__ __half sA[128*G3PITCH];
    __shared__ __half sB[64*G3PITCH];
    int pt = blockIdx.x, bh = blockIdx.y;
    int b = bh >> 3, head = bh & 7;
    int tid = threadIdx.x, wid = tid >> 5, lane = tid & 31;
    int wm = wid >> 1, wn = wid & 1;   // 4 x 2 warps, 32x32 warp tiles
    const __half* Aq = g_qs + ((size_t)bh*HW + pt*128)*DH;
    const __half* Bc = g_ctxT + (size_t)bh*4096;
    #pragma unroll
    for (int i = 0; i < 4; i++) {           // A: 128 rows x 64 halfs = 1024 cp16
        int e = tid + (i << 8);
        int r = e >> 3, q = e & 7;
        cp16(smem_u32(&sA[r*G3PITCH + q*8]), Aq + (size_t)r*DH + q*8);
    }
    #pragma unroll
    for (int i = 0; i < 2; i++) {           // B: 64 x 64 = 512 cp16
        int e = tid + (i << 8);
        int r = e >> 3, q = e & 7;
        cp16(smem_u32(&sB[r*G3PITCH + q*8]), Bc + (size_t)r*DH + q*8);
    }
    CP_COMMIT(); CP_WAIT0();
    __syncthreads();

    float acc[2][4][4] = {};
    int lrow = (lane & 7) + (((lane >> 3) & 1) << 3);
    int lcol = (lane >> 4) << 3;
    #pragma unroll
    for (int ks = 0; ks < 4; ks++) {
        int kof = ks*16 + lcol;
        uint32_t bf[2][4];
        #pragma unroll
        for (int bt = 0; bt < 2; bt++) {
            int row = wn*32 + bt*16 + lrow;
            ldmx4(bf[bt], smem_u32(&sB[row*G3PITCH + kof]));
        }
        #pragma unroll
        for (int mt = 0; mt < 2; mt++) {
            uint32_t af[4];
            int row = wm*32 + mt*16 + lrow;
            ldmx4(af, smem_u32(&sA[row*G3PITCH + kof]));
            #pragma unroll
            for (int nt = 0; nt < 4; nt++) {
                int bt = nt >> 1, od = nt & 1;
                mma_f16(acc[mt][nt], af, bf[bt][od], bf[bt][od+2]);
            }
        }
    }
    // store a3 fp16: row p = pt*128 + r, col = head*64 + e. Frag col-pairs contiguous.
    __half2* a3b = (__half2*)(g_a3 + ((size_t)b*HW + (size_t)pt*128)*HID + head*DH);
    #pragma unroll
    for (int mt = 0; mt < 2; mt++) {
        int rml = wm*32 + mt*16 + (lane >> 2);
        #pragma unroll
        for (int nt = 0; nt < 4; nt++) {
            int cl = wn*32 + nt*8 + 2*(lane & 3);
            float* d = acc[mt][nt];
            a3b[(size_t)rml*(HID/2) + (cl >> 1)]     = __floats2half2_rn(d[0]*A3SCALE, d[1]*A3SCALE);
            a3b[(size_t)(rml+8)*(HID/2) + (cl >> 1)] = __floats2half2_rn(d[2]*A3SCALE, d[3]*A3SCALE);
        }
    }
}

// ==================== launch ====================
#define SMEM_G1 68096    /* max(3*20480=61440, 128*130*4=66560) + 1536 */
#define SMEM_G4 80384    /* max(3*25600=76800, 256*68*4=69632)  + 3584 */

extern "C" void kernel_launch(void* const* d_in, const int* in_sizes, int n_in,
                              void* d_out, int out_size) {
    const float* feat = (const float*)d_in[0];
    const float* gin  = (const float*)d_in[1];
    const float* wqkv = (const float*)d_in[2];
    const float* wout = (const float*)d_in[3];
    const float* gout = (const float*)d_in[4];
    float* out = (float*)d_out;

    cudaFuncSetAttribute(gemm_p<128,128,256,true>,
                         cudaFuncAttributeMaxDynamicSharedMemorySize, SMEM_G1);
    cudaFuncSetAttribute(gemm_p<256,64,512,false>,
                         cudaFuncAttributeMaxDynamicSharedMemorySize, SMEM_G4);
    cudaFuncSetAttribute(gemm2,
                         cudaFuncAttributeMaxDynamicSharedMemorySize, SMEM_G2);

    prep_w1b<<<OQKV, 256>>>(wqkv, gin);
    prep_w2b<<<CCH, 256>>>(wout);
    conv_feat<<<dim3(HW/64, BATCH), 256>>>(feat);
    gemm_p<128,128,256,true><<<dim3(HW/128, OQKV/128, BATCH), 256, SMEM_G1>>>(nullptr, nullptr);
    kmerge<<<BHN*DH/8, 256>>>();
    gemm2<<<dim3(8, BHN), 256, SMEM_G2>>>();
    ctxred<<<BHN, 256>>>();
    gemm3<<<dim3(HW/128, BHN), 256>>>();
    gemm_p<256,64,512,false><<<dim3(HW/64, 1, BATCH), 256, SMEM_G4>>>(out, gout);
}

// round 15
// speedup vs baseline: 1.3550x; 1.0340x over previous
#include <cuda_runtime.h>
#include <cuda_fp16.h>
#include <math.h>
#include <stdint.h>

#define BATCH 16
#define CCH   256
#define HW    4096
#define HEADS 8
#define DH    64
#define HID   512
#define OQKV  1536
#define BHN   (BATCH*HEADS)   /* 128 */
#define QSCALE 0.125f
#define LNEPS  1e-5f
#define INV_N  (1.0f/4096.0f)
#define PIT   72   /* smem row pitch for 64-half rows: 144B -> 8 ldmatrix rows on distinct banks */
// a3 = (qs @ ctx_noInvN) * A3SCALE; ctx carries no 1/N, so A3SCALE = 2^18/4096 = 64.
#define A3SCALE    64.0f
#define A3UNSCALE  (1.0f/262144.0f)

// ==================== scratch (device globals; no allocations) ====================
__device__ __align__(256) float g_stat1[BATCH*HW*2];
__device__ __align__(256) float g_ws[OQKV];
__device__ __align__(256) __half g_w1[OQKV*CCH];
__device__ __align__(256) __half g_w2[CCH*HID];
__device__ __align__(256) __half g_fT[(size_t)BATCH*HW*CCH];
__device__ __align__(256) __half g_kv[(size_t)BATCH*1024*HW];
__device__ __align__(256) __half g_qs[(size_t)BHN*HW*DH];
__device__ __align__(256) float g_kpm[32*BHN*DH];
__device__ __align__(256) float g_kps[32*BHN*DH];
__device__ __align__(256) float g_kmax[BHN*DH];
__device__ __align__(256) float g_ksum[BHN*DH];
__device__ __align__(256) float g_ctxp[8*BHN*DH*DH];
__device__ __align__(256) __half g_ctxT[BHN*DH*DH];             // ctx^T fp16 [bh][e][d], NO 1/N
__device__ __align__(256) __half g_a3[(size_t)BATCH*HW*HID];

// ==================== helpers (sm_80+ PTX, valid on sm_100) ====================
__device__ __forceinline__ uint32_t smem_u32(const void* p) {
    uint32_t a;
    asm("{ .reg .u64 t; cvta.to.shared.u64 t, %1; cvt.u32.u64 %0, t; }" : "=r"(a) : "l"(p));
    return a;
}
__device__ __forceinline__ void ldmx4(uint32_t* r, uint32_t a) {
    asm volatile("ldmatrix.sync.aligned.m8n8.x4.shared.b16 {%0,%1,%2,%3}, [%4];"
        : "=r"(r[0]), "=r"(r[1]), "=r"(r[2]), "=r"(r[3]) : "r"(a));
}
__device__ __forceinline__ void mma_f16(float* d, const uint32_t* a, uint32_t b0, uint32_t b1) {
    asm volatile("mma.sync.aligned.m16n8k16.row.col.f32.f16.f16.f32 "
        "{%0,%1,%2,%3}, {%4,%5,%6,%7}, {%8,%9}, {%0,%1,%2,%3};"
        : "+f"(d[0]), "+f"(d[1]), "+f"(d[2]), "+f"(d[3])
        : "r"(a[0]), "r"(a[1]), "r"(a[2]), "r"(a[3]), "r"(b0), "r"(b1));
}
__device__ __forceinline__ void cp16(uint32_t s, const void* g) {
    asm volatile("cp.async.cg.shared.global [%0], [%1], 16;" :: "r"(s), "l"(g) : "memory");
}
#define CP_COMMIT() asm volatile("cp.async.commit_group;" ::: "memory")
#define CP_WAIT1()  asm volatile("cp.async.wait_group 1;" ::: "memory")
#define CP_WAIT0()  asm volatile("cp.async.wait_group 0;" ::: "memory")

// ==================== weight prep (single fp16) ====================
__global__ void __launch_bounds__(256) prep_w1b(const float* __restrict__ wqkv,
                                                const float* __restrict__ gin) {
    int o = blockIdx.x, c = threadIdx.x;
    float w = wqkv[o*CCH + c] * gin[c];
    __half h = __float2half_rn(w);
    g_w1[o*CCH + c] = h;
    float we = __half2float(h);
    __shared__ float red[256];
    red[c] = we; __syncthreads();
    for (int s = 128; s > 0; s >>= 1) { if (c < s) red[c] += red[c+s]; __syncthreads(); }
    if (c == 0) g_ws[o] = red[0];
}

__global__ void __launch_bounds__(256) prep_w2b(const float* __restrict__ wout) {
    int o = blockIdx.x;
    for (int t = threadIdx.x; t < HID; t += 256)
        g_w2[o*HID + t] = __float2half_rn(wout[o*HID + t]);
}

// ==================== feature transpose + fp16 + LN stats (fused) ====================
__global__ void __launch_bounds__(256) conv_feat(const float* __restrict__ feat) {
    __shared__ float S[128][65];
    __shared__ float s_s[256], s_ss[256];
    int p0 = blockIdx.x*64, b = blockIdx.y;
    int tid = threadIdx.x;
    float sum = 0.f, ssum = 0.f;
    for (int h = 0; h < 2; h++) {
        #pragma unroll
        for (int i = 0; i < 32; i++) {
            int idx = tid + (i<<8);
            int cl = idx >> 6, pl = idx & 63;
            float v = feat[((size_t)(b*CCH + h*128 + cl))*HW + p0 + pl];
            S[cl][pl] = v;
            sum += v; ssum = fmaf(v, v, ssum);
        }
        __syncthreads();
        #pragma unroll
        for (int i = 0; i < 32; i++) {
            int idx = tid + (i<<8);
            int pl = idx >> 7, cl = idx & 127;
            g_fT[((size_t)b*HW + p0 + pl)*CCH + h*128 + cl] = __float2half_rn(S[cl][pl]);
        }
        __syncthreads();
    }
    s_s[tid] = sum; s_ss[tid] = ssum;
    __syncthreads();
    if (tid < 64) {
        float s  = s_s[tid] + s_s[tid+64] + s_s[tid+128] + s_s[tid+192];
        float ss = s_ss[tid] + s_ss[tid+64] + s_ss[tid+128] + s_ss[tid+192];
        float mu = s * (1.f/CCH);
        float var = fmaf(-mu, mu, ss * (1.f/CCH));
        ((float2*)g_stat1)[(size_t)b*HW + p0 + tid] = make_float2(mu, rsqrtf(var + LNEPS));
    }
}

// ==================== warp-MMA GEMM (8 warps, 64x32 tiles, 64-wide K chunks) ====================
// G1=true : TM=128,TN=128,K=256, 3-stage/1-barrier (4 chunks). Region epilogues.
// G1=false: TM=256,TN=64, K=512, 2-stage/1-barrier (8 chunks). Output-LN epilogue.
template<int TM, int TN, int KTOT, bool G1>
__global__ void __launch_bounds__(256, 2) gemm_p(float* __restrict__ Cext,
                                                 const float* __restrict__ gout) {
    extern __shared__ char smem[];
    constexpr int WN     = TN/32;
    constexpr int A_ARR  = TM*PIT*2;
    constexpr int B_ARR  = TN*PIT*2;
    constexpr int STAGE  = A_ARR + B_ARR;
    constexpr int NSTG   = G1 ? 3 : 2;
    constexpr int BUFB   = TM*(G1 ? (TN+2) : (TN+4))*4;
    constexpr int FIX    = (NSTG*STAGE > BUFB) ? NSTG*STAGE : BUFB;
    constexpr int KC     = KTOT/64;

    int tid = threadIdx.x, wid = tid >> 5, lane = tid & 31;
    int b = blockIdx.z, m0 = blockIdx.y*TM, n0 = blockIdx.x*TN;
    int wm = wid / WN, wn = wid % WN;
    uint32_t sb = smem_u32(smem);

    const __half* Ap = (G1 ? g_w1 : g_w2) + (size_t)m0*KTOT;
    const __half* Bp = (G1 ? g_fT : g_a3) + ((size_t)b*HW + n0)*KTOT;

    float2* sstat = (float2*)(smem + FIX);          // G1
    float*  sws   = (float*)(smem + FIX + 1024);    // G1
    float*  sg    = (float*)(smem + FIX);           // G4
    float*  ps    = (float*)(smem + FIX + 1024);    // G4
    float*  pss   = (float*)(smem + FIX + 2048);    // G4
    float2* mrs   = (float2*)(smem + FIX + 3072);   // G4

    if (G1) {
        if (tid < 128) sstat[tid] = ((const float2*)g_stat1)[(size_t)b*HW + n0 + tid];
        else           sws[tid-128] = g_ws[m0 + tid - 128];
    } else {
        sg[tid] = gout[tid];
    }

    auto load_stage = [&](int kc, int s) {
        #pragma unroll
        for (int i = 0; i < TM/32; i++) {             // A: TM rows x 64 halfs
            int e = tid + (i << 8);
            int r = e >> 3, q = e & 7;
            cp16(sb + s*STAGE + (r*PIT + q*8)*2, Ap + (size_t)r*KTOT + kc*64 + q*8);
        }
        #pragma unroll
        for (int i = 0; i < TN/32; i++) {             // B: TN rows x 64 halfs
            int e = tid + (i << 8);
            int r = e >> 3, q = e & 7;
            cp16(sb + s*STAGE + A_ARR + (r*PIT + q*8)*2, Bp + (size_t)r*KTOT + kc*64 + q*8);
        }
    };

    float acc[4][4][4] = {};
    int lrow = (lane & 7) + (((lane >> 3) & 1) << 3);
    int lcol = (lane >> 4) << 3;

    auto compute_stage = [&](int s) {
        uint32_t sbase = sb + s*STAGE;
        #pragma unroll
        for (int ks = 0; ks < 4; ks++) {
            int kof = ks*16 + lcol;
            uint32_t bf[2][4];
            #pragma unroll
            for (int bt = 0; bt < 2; bt++) {
                int row = wn*32 + bt*16 + lrow;
                ldmx4(bf[bt], sbase + A_ARR + (row*PIT + kof)*2);
            }
            #pragma unroll
            for (int mt = 0; mt < 4; mt++) {
                uint32_t af[4];
                int row = wm*64 + mt*16 + lrow;
                ldmx4(af, sbase + (row*PIT + kof)*2);
                #pragma unroll
                for (int nt = 0; nt < 4; nt++) {
                    int bt = nt >> 1, od = nt & 1;
                    mma_f16(acc[mt][nt], af, bf[bt][od], bf[bt][od+2]);
                }
            }
        }
    };

    if (G1) {
        // 3-stage, 1 barrier per 64-K chunk (KC=4)
        load_stage(0, 0); CP_COMMIT();
        load_stage(1, 1); CP_COMMIT();
        #pragma unroll
        for (int kc = 0; kc < KC; kc++) {
            if (kc + 1 < KC) { CP_WAIT1(); } else { CP_WAIT0(); }
            __syncthreads();
            if (kc + 2 < KC) {
                load_stage(kc+2, (kc+2) % 3); CP_COMMIT();
            }
            compute_stage(kc % 3);
        }
        __syncthreads();
    } else {
        // 2-stage, 1 barrier per 64-K chunk (KC=8)
        load_stage(0, 0); CP_COMMIT();
        #pragma unroll
        for (int kc = 0; kc < KC; kc++) {
            CP_WAIT0();
            __syncthreads();
            if (kc + 1 < KC) { load_stage(kc+1, (kc+1) & 1); CP_COMMIT(); }
            compute_stage(kc & 1);
        }
        __syncthreads();
    }

    if (G1) {
        float* buf = (float*)smem;   // 128 x 128, pitch 130
        #pragma unroll
        for (int mt = 0; mt < 4; mt++) {
            int rml = wm*64 + mt*16 + (lane >> 2);
            #pragma unroll
            for (int nt = 0; nt < 4; nt++) {
                int cl = wn*32 + nt*8 + 2*(lane & 3);
                float* d = acc[mt][nt];
                float2 s0 = sstat[cl], s1 = sstat[cl+1];
                float w0 = sws[rml], w1 = sws[rml+8];
                buf[rml*130 + cl]       = s0.y*(d[0] - s0.x*w0);
                buf[rml*130 + cl + 1]   = s1.y*(d[1] - s1.x*w0);
                buf[(rml+8)*130 + cl]     = s0.y*(d[2] - s0.x*w1);
                buf[(rml+8)*130 + cl + 1] = s1.y*(d[3] - s1.x*w1);
            }
        }
        __syncthreads();
        int region = blockIdx.y >> 2;
        if (region == 0) {
            int col = tid & 127, g = tid >> 7;
            int p = n0 + col, h2 = p >> 6, wi = p & 63;
            int bh = b*8 + blockIdx.y*2 + g;
            float mx = -1e30f;
            #pragma unroll 8
            for (int d = 0; d < 64; d++) mx = fmaxf(mx, buf[(g*64+d)*130 + col]);
            float sum = 0.f;
            #pragma unroll 8
            for (int d = 0; d < 64; d++) {
                float e = __expf(buf[(g*64+d)*130 + col] - mx);
                buf[(g*64+d)*130 + col] = e;
                sum += e;
            }
            float r = QSCALE / sum;
            uint4* dst = (uint4*)&g_qs[((size_t)bh*HW + wi*64 + h2)*DH];
            #pragma unroll
            for (int d8 = 0; d8 < 8; d8++) {
                __half2 h0 = __floats2half2_rn(buf[(g*64+d8*8+0)*130+col]*r, buf[(g*64+d8*8+1)*130+col]*r);
                __half2 h1 = __floats2half2_rn(buf[(g*64+d8*8+2)*130+col]*r, buf[(g*64+d8*8+3)*130+col]*r);
                __half2 h2v= __floats2half2_rn(buf[(g*64+d8*8+4)*130+col]*r, buf[(g*64+d8*8+5)*130+col]*r);
                __half2 h3 = __floats2half2_rn(buf[(g*64+d8*8+6)*130+col]*r, buf[(g*64+d8*8+7)*130+col]*r);
                uint4 u;
                u.x = *(uint32_t*)&h0; u.y = *(uint32_t*)&h1;
                u.z = *(uint32_t*)&h2v; u.w = *(uint32_t*)&h3;
                dst[d8] = u;
            }
        } else if (region == 1) {
            int row = tid >> 1, half = tid & 1;
            float m = -1e30f;
            #pragma unroll 8
            for (int c = half*64; c < half*64 + 64; c++) m = fmaxf(m, buf[row*130 + c]);
            float om = __shfl_xor_sync(0xffffffffu, m, 1);
            float M = fmaxf(m, om);
            __half2* kvb = (__half2*)(g_kv + ((size_t)(b*1024 + (m0 - 512)))*HW + n0);
            float s = 0.f;
            #pragma unroll 8
            for (int c2 = 0; c2 < 32; c2++) {
                int c = half*64 + 2*c2;
                float e0 = __expf(buf[row*130 + c]     - M);
                float e1 = __expf(buf[row*130 + c + 1] - M);
                s += e0 + e1;
                kvb[(size_t)row*(HW/2) + half*32 + c2] = __floats2half2_rn(e0, e1);
            }
            float os = __shfl_xor_sync(0xffffffffu, s, 1);
            float S = s + os;
            if (half == 0) {
                int ch = (blockIdx.y - 4)*128 + row;
                int r = (b*8 + (ch >> 6))*64 + (ch & 63);
                g_kpm[blockIdx.x*(BHN*DH) + r] = M;
                g_kps[blockIdx.x*(BHN*DH) + r] = S;
            }
        } else {
            float* sinv2 = (float*)(smem + FIX);
            int col = tid & 127, g = tid >> 7;
            float ss = 0.f;
            #pragma unroll 8
            for (int d = 0; d < 64; d++) {
                float v = buf[(g*64+d)*130 + col];
                ss = fmaf(v, v, ss);
            }
            sinv2[g*128 + col] = 1.f / fmaxf(sqrtf(ss), 1e-12f);
            __syncthreads();
            __half2* kvb = (__half2*)(g_kv + ((size_t)(b*1024 + (m0 - 512)))*HW + n0);
            #pragma unroll 8
            for (int i = 0; i < 32; i++) {
                int idx = tid + (i << 8);
                int row = idx >> 6, c2 = idx & 63;
                int gg = row >> 6;
                float v0 = buf[row*130 + 2*c2]     * sinv2[gg*128 + 2*c2];
                float v1 = buf[row*130 + 2*c2 + 1] * sinv2[gg*128 + 2*c2 + 1];
                kvb[(size_t)row*(HW/2) + c2] = __floats2half2_rn(v0, v1);
            }
        }
    } else {
        float* buf = (float*)smem;   // 256 x 64, pitch 68
        float* Cb = Cext + ((size_t)(b*CCH + m0))*HW + n0;
        #pragma unroll
        for (int mt = 0; mt < 4; mt++) {
            int rml = wm*64 + mt*16 + (lane >> 2);
            #pragma unroll
            for (int nt = 0; nt < 4; nt++) {
                int cl = wn*32 + nt*8 + 2*(lane & 3);
                float* d = acc[mt][nt];
                buf[rml*68 + cl]     = d[0] * A3UNSCALE;
                buf[rml*68 + cl + 1] = d[1] * A3UNSCALE;
                buf[(rml+8)*68 + cl]     = d[2] * A3UNSCALE;
                buf[(rml+8)*68 + cl + 1] = d[3] * A3UNSCALE;
            }
        }
        __syncthreads();
        {
            int col = tid & 63, part = tid >> 6;
            float s = 0.f, ss = 0.f;
            #pragma unroll 8
            for (int r = part*64; r < part*64 + 64; r++) {
                float v = buf[r*68 + col];
                s += v; ss = fmaf(v, v, ss);
            }
            ps[part*64 + col] = s;
            pss[part*64 + col] = ss;
        }
        __syncthreads();
        if (tid < 64) {
            float s  = ps[tid] + ps[64+tid] + ps[128+tid] + ps[192+tid];
            float ss = pss[tid] + pss[64+tid] + pss[128+tid] + pss[192+tid];
            float mu = s * (1.f/CCH);
            float var = fmaf(-mu, mu, ss * (1.f/CCH));
            mrs[tid] = make_float2(mu, rsqrtf(var + LNEPS));
        }
        __syncthreads();
        #pragma unroll 8
        for (int i = 0; i < 64; i++) {
            int idx = tid + (i << 8);
            int row = idx >> 6, col = idx & 63;
            float2 st = mrs[col];
            Cb[(size_t)row*HW + col] = (buf[row*68 + col] - st.x) * st.y * sg[row];
        }
    }
}

// ==================== merge k-softmax partials over 32 tiles ====================
__global__ void __launch_bounds__(256) kmerge() {
    int r = blockIdx.x*8 + (threadIdx.x >> 5);
    int lane = threadIdx.x & 31;
    float m = g_kpm[lane*(BHN*DH) + r];
    float s = g_kps[lane*(BHN*DH) + r];
    float M = m;
    #pragma unroll
    for (int o = 16; o > 0; o >>= 1) M = fmaxf(M, __shfl_xor_sync(0xffffffffu, M, o));
    float sc = s * __expf(m - M);
    #pragma unroll
    for (int o = 16; o > 0; o >>= 1) sc += __shfl_xor_sync(0xffffffffu, sc, o);
    if (lane == 0) { g_kmax[r] = M; g_ksum[r] = sc; }
}

// ==================== context partials: tensor-core MMA over exp'd k / scaled v ====================
#define G2PITCH 136
#define G2TILE  (64*G2PITCH*2)
#define G2STG   (2*G2TILE)
#define SMEM_G2 (2*G2STG)

__global__ void __launch_bounds__(256, 2) gemm2() {
    extern __shared__ char smem[];
    uint32_t sb = smem_u32(smem);
    int sp = blockIdx.x, bh = blockIdx.y;
    int b = bh >> 3, head = bh & 7;
    int tid = threadIdx.x, wid = tid >> 5, lane = tid & 31;
    int wm = wid >> 1, wn = wid & 1;
    const __half* kbase = g_kv + ((size_t)(b*1024 + head*DH))*HW;
    const __half* vbase = g_kv + ((size_t)(b*1024 + 512 + head*DH))*HW;
    int n0 = sp*512;

    int r0 = wm*16 + (lane >> 2), r1 = r0 + 8;
    float km0 = g_kmax[bh*64 + r0], km1 = g_kmax[bh*64 + r1];
    float rs0 = 1.f / g_ksum[bh*64 + r0], rs1 = 1.f / g_ksum[bh*64 + r1];

    auto load_blk = [&](int blk, int s) {
        int nb = n0 + blk*128;
        #pragma unroll
        for (int i = 0; i < 8; i++) {
            int e = tid + (i << 8);
            int isv = e >= 1024;
            int rq = e & 1023;
            int r = rq >> 4, q = rq & 15;
            const __half* src = (isv ? vbase : kbase) + (size_t)r*HW + nb + q*8;
            cp16(sb + s*G2STG + isv*G2TILE + (r*G2PITCH + q*8)*2, src);
        }
    };

    float accT[4][4] = {};
    int lrow = (lane & 7) + (((lane >> 3) & 1) << 3);
    int lcol = (lane >> 4) << 3;

    load_blk(0, 0); CP_COMMIT();
    #pragma unroll
    for (int blk = 0; blk < 4; blk++) {
        if (blk + 1 < 4) { load_blk(blk+1, (blk+1) & 1); }
        CP_COMMIT();
        if (blk + 1 < 4) { CP_WAIT1(); } else { CP_WAIT0(); }
        __syncthreads();
        uint32_t base = sb + (blk & 1)*G2STG;
        float accB[4][4] = {};
        #pragma unroll
        for (int ks = 0; ks < 8; ks++) {
            int kof = ks*16 + lcol;
            uint32_t af[4];
            {
                int row = wm*16 + lrow;
                ldmx4(af, base + (row*G2PITCH + kof)*2);
            }
            uint32_t bf[2][4];
            #pragma unroll
            for (int bt = 0; bt < 2; bt++) {
                int row = wn*32 + bt*16 + lrow;
                ldmx4(bf[bt], base + G2TILE + (row*G2PITCH + kof)*2);
            }
            #pragma unroll
            for (int nt = 0; nt < 4; nt++) {
                int bt = nt >> 1, od = nt & 1;
                mma_f16(accB[nt], af, bf[bt][od], bf[bt][od+2]);
            }
        }
        int tile = sp*4 + blk;
        float sc0 = __expf(g_kpm[(size_t)tile*(BHN*DH) + bh*64 + r0] - km0) * rs0;
        float sc1 = __expf(g_kpm[(size_t)tile*(BHN*DH) + bh*64 + r1] - km1) * rs1;
        #pragma unroll
        for (int nt = 0; nt < 4; nt++) {
            accT[nt][0] = fmaf(sc0, accB[nt][0], accT[nt][0]);
            accT[nt][1] = fmaf(sc0, accB[nt][1], accT[nt][1]);
            accT[nt][2] = fmaf(sc1, accB[nt][2], accT[nt][2]);
            accT[nt][3] = fmaf(sc1, accB[nt][3], accT[nt][3]);
        }
        __syncthreads();
    }
    float* cp = g_ctxp + ((size_t)(sp*BHN + bh))*4096;
    #pragma unroll
    for (int nt = 0; nt < 4; nt++) {
        int cl = wn*32 + nt*8 + 2*(lane & 3);
        *(float2*)&cp[r0*64 + cl] = make_float2(accT[nt][0], accT[nt][1]);
        *(float2*)&cp[r1*64 + cl] = make_float2(accT[nt][2], accT[nt][3]);
    }
}

// ==================== reduce split-K partials, transpose, fp16 (NO 1/N) ====================
__global__ void __launch_bounds__(256) ctxred() {
    __shared__ float T[64][65];
    int bh = blockIdx.x, tid = threadIdx.x;
    for (int i = tid; i < 4096; i += 256) {
        float s = 0.f;
        #pragma unroll
        for (int sp = 0; sp < 8; sp++) s += g_ctxp[((size_t)(sp*BHN + bh))*4096 + i];
        T[i >> 6][i & 63] = s;
    }
    __syncthreads();
    for (int i = tid; i < 4096; i += 256) {
        int e = i >> 6, d = i & 63;
        g_ctxT[(size_t)bh*4096 + i] = __float2half_rn(T[d][e]);
    }
}

// ==================== gemm3 (tensor-core): a3 = (qs @ ctx) * A3SCALE -> fp16 ====================
#define G3PITCH 72
__global__ void __launch_bounds__(256) gemm3() {
    __shared__ __half sA[128*G3PITCH];
    __shared__ __half sB[64*G3PITCH];
    int pt = blockIdx.x, bh = blockIdx.y;
    int b = bh >> 3, head = bh & 7;
    int tid = threadIdx.x, wid = tid >> 5, lane = tid & 31;
    int wm = wid >> 1, wn = wid & 1;
    const __half* Aq = g_qs + ((size_t)bh*HW + pt*128)*DH;
    const __half* Bc = g_ctxT + (size_t)bh*4096;
    #pragma unroll
    for (int i = 0; i < 4; i++) {
        int e = tid + (i << 8);
        int r = e >> 3, q = e & 7;
        cp16(smem_u32(&sA[r*G3PITCH + q*8]), Aq + (size_t)r*DH + q*8);
    }
    #pragma unroll
    for (int i = 0; i < 2; i++) {
        int e = tid + (i << 8);
        int r = e >> 3, q = e & 7;
        cp16(smem_u32(&sB[r*G3PITCH + q*8]), Bc + (size_t)r*DH + q*8);
    }
    CP_COMMIT(); CP_WAIT0();
    __syncthreads();

    float acc[2][4][4] = {};
    int lrow = (lane & 7) + (((lane >> 3) & 1) << 3);
    int lcol = (lane >> 4) << 3;
    #pragma unroll
    for (int ks = 0; ks < 4; ks++) {
        int kof = ks*16 + lcol;
        uint32_t bf[2][4];
        #pragma unroll
        for (int bt = 0; bt < 2; bt++) {
            int row = wn*32 + bt*16 + lrow;
            ldmx4(bf[bt], smem_u32(&sB[row*G3PITCH + kof]));
        }
        #pragma unroll
        for (int mt = 0; mt < 2; mt++) {
            uint32_t af[4];
            int row = wm*32 + mt*16 + lrow;
            ldmx4(af, smem_u32(&sA[row*G3PITCH + kof]));
            #pragma unroll
            for (int nt = 0; nt < 4; nt++) {
                int bt = nt >> 1, od = nt & 1;
                mma_f16(acc[mt][nt], af, bf[bt][od], bf[bt][od+2]);
            }
        }
    }
    __half2* a3b = (__half2*)(g_a3 + ((size_t)b*HW + (size_t)pt*128)*HID + head*DH);
    #pragma unroll
    for (int mt = 0; mt < 2; mt++) {
        int rml = wm*32 + mt*16 + (lane >> 2);
        #pragma unroll
        for (int nt = 0; nt < 4; nt++) {
            int cl = wn*32 + nt*8 + 2*(lane & 3);
            float* d = acc[mt][nt];
            a3b[(size_t)rml*(HID/2) + (cl >> 1)]     = __floats2half2_rn(d[0]*A3SCALE, d[1]*A3SCALE);
            a3b[(size_t)(rml+8)*(HID/2) + (cl >> 1)] = __floats2half2_rn(d[2]*A3SCALE, d[3]*A3SCALE);
        }
    }
}

// ==================== launch ====================
#define SMEM_G1 112128   /* 3*36864 = 110592 (> 128*130*4=66560) + 1536 */
#define SMEM_G4 95744    /* 2*46080 = 92160 (> 256*68*4=69632)   + 3584 */

extern "C" void kernel_launch(void* const* d_in, const int* in_sizes, int n_in,
                              void* d_out, int out_size) {
    const float* feat = (const float*)d_in[0];
    const float* gin  = (const float*)d_in[1];
    const float* wqkv = (const float*)d_in[2];
    const float* wout = (const float*)d_in[3];
    const float* gout = (const float*)d_in[4];
    float* out = (float*)d_out;

    cudaFuncSetAttribute(gemm_p<128,128,256,true>,
                         cudaFuncAttributeMaxDynamicSharedMemorySize, SMEM_G1);
    cudaFuncSetAttribute(gemm_p<256,64,512,false>,
                         cudaFuncAttributeMaxDynamicSharedMemorySize, SMEM_G4);
    cudaFuncSetAttribute(gemm2,
                         cudaFuncAttributeMaxDynamicSharedMemorySize, SMEM_G2);

    prep_w1b<<<OQKV, 256>>>(wqkv, gin);
    prep_w2b<<<CCH, 256>>>(wout);
    conv_feat<<<dim3(HW/64, BATCH), 256>>>(feat);
    gemm_p<128,128,256,true><<<dim3(HW/128, OQKV/128, BATCH), 256, SMEM_G1>>>(nullptr, nullptr);
    kmerge<<<BHN*DH/8, 256>>>();
    gemm2<<<dim3(8, BHN), 256, SMEM_G2>>>();
    ctxred<<<BHN, 256>>>();
    gemm3<<<dim3(HW/128, BHN), 256>>>();
    gemm_p<256,64,512,false><<<dim3(HW/64, 1, BATCH), 256, SMEM_G4>>>(out, gout);
}